// round 5
// baseline (speedup 1.0000x reference)
#include <cuda_runtime.h>
#include <cuda_bf16.h>
#include <cstdint>
#include <math.h>

#define Bb   8
#define Cc   32
#define Ll   90000
#define DOWNL 22500
#define FLATN 1440000

// ---- scratch ----
__device__ float g_hA[Bb*Cc*Ll];
__device__ float g_hB[Bb*Cc*Ll];
__device__ float g_skip[Bb*Cc*Ll];
__device__ float g_y[Bb*FLATN];
__device__ float g_o[Bb*64];

__device__ __forceinline__ float fsig(float x)  { return 1.0f / (1.0f + __expf(-x)); }
__device__ __forceinline__ float ftanh(float x) { return 2.0f * fsig(2.0f * x) - 1.0f; }

__device__ __forceinline__ void mma_bf16(float d[4], const uint32_t a[4], const uint32_t b[2]) {
    asm volatile(
        "mma.sync.aligned.m16n8k16.row.col.f32.bf16.bf16.f32 "
        "{%0,%1,%2,%3}, {%4,%5,%6,%7}, {%8,%9}, {%0,%1,%2,%3};"
        : "+f"(d[0]), "+f"(d[1]), "+f"(d[2]), "+f"(d[3])
        : "r"(a[0]), "r"(a[1]), "r"(a[2]), "r"(a[3]), "r"(b[0]), "r"(b[1]));
}
__device__ __forceinline__ uint32_t ld32(const __nv_bfloat16* p) {
    return *(const uint32_t*)p;
}

// SMEM strides (bf16 elements) — chosen for conflict-free fragment access
#define STR_A  74      // A tiles [128][64]:  row = 148 B
#define STR_W1 72      // W1 [64][64]:        row = 144 B
#define STR_W2 40      // W2 [64][32]:        row = 80 B
#define STR_O  40      // O  [128][32]:       row = 80 B
#define STR_S  33      // f32 staging [128][32]

// byte offsets in dynamic smem
#define OFF_AHI   0
#define OFF_ALO   18944
#define OFF_W1HI  37888
#define OFF_W1LO  47104
#define OFF_W2HI  56320
#define OFF_W2LO  61440
#define OFF_OHI   66560
#define OFF_OLO   76800
#define OFF_S     87040
#define OFF_BIAS  103936
#define SMEM_BLK  104448

// ---------------- conv0 ----------------
__global__ void conv0_kernel(const float* __restrict__ x,
                             const float* __restrict__ w0,
                             const float* __restrict__ b0)
{
    int t  = blockIdx.x * blockDim.x + threadIdx.x;
    int bc = blockIdx.y;
    if (t >= Ll) return;
    int b = bc >> 5, c = bc & 31;
    const float* xb = x + b * Ll;
    float wk0 = w0[c*3+0], wk1 = w0[c*3+1], wk2 = w0[c*3+2];
    float v = wk2 * xb[t] + b0[c];
    if (t >= 1) v += wk1 * xb[t-1];
    if (t >= 2) v += wk0 * xb[t-2];
    g_hA[(b*Cc + c)*Ll + t] = v;
}

// ---------------- WaveNet block via mma.sync bf16 (split hi/lo) ----------------
template<bool FIRST>
__global__ void __launch_bounds__(256, 2)
wn_block_mma(int ping, int dil,
             const float* __restrict__ Wf, const float* __restrict__ Wg,
             const float* __restrict__ Ws, const float* __restrict__ Wr,
             const float* __restrict__ bfp, const float* __restrict__ bgp,
             const float* __restrict__ bsp, const float* __restrict__ brp)
{
    extern __shared__ char sm[];
    __nv_bfloat16* sAhi  = (__nv_bfloat16*)(sm + OFF_AHI);
    __nv_bfloat16* sAlo  = (__nv_bfloat16*)(sm + OFF_ALO);
    __nv_bfloat16* sW1hi = (__nv_bfloat16*)(sm + OFF_W1HI);
    __nv_bfloat16* sW1lo = (__nv_bfloat16*)(sm + OFF_W1LO);
    __nv_bfloat16* sW2hi = (__nv_bfloat16*)(sm + OFF_W2HI);
    __nv_bfloat16* sW2lo = (__nv_bfloat16*)(sm + OFF_W2LO);
    __nv_bfloat16* sOhi  = (__nv_bfloat16*)(sm + OFF_OHI);
    __nv_bfloat16* sOlo  = (__nv_bfloat16*)(sm + OFF_OLO);
    float* sS    = (float*)(sm + OFF_S);
    float* sS2   = (float*)(sm + OFF_OHI);    // aliases sO region after GEMM2
    float* sBias = (float*)(sm + OFF_BIAS);

    const float* h_in  = ping ? g_hB : g_hA;
    float*       h_out = ping ? g_hA : g_hB;

    const int tid = threadIdx.x;
    const int b   = blockIdx.y;
    const int t0  = blockIdx.x * 128;
    const float* hb = h_in + (size_t)b * Cc * Ll;

    // ---- fill W1 [64n][64k] hi/lo ----
    for (int e = tid; e < 4096; e += 256) {
        int n = e >> 6, k = e & 63;
        float wv = (n < 32)
            ? ((k < 32) ? Wf[n*64 + k*2 + 0] : Wf[n*64 + (k-32)*2 + 1])
            : ((k < 32) ? Wg[(n-32)*64 + k*2 + 0] : Wg[(n-32)*64 + (k-32)*2 + 1]);
        __nv_bfloat16 hi = __float2bfloat16_rn(wv);
        __nv_bfloat16 lo = __float2bfloat16_rn(wv - __bfloat162float(hi));
        sW1hi[n*STR_W1 + k] = hi;
        sW1lo[n*STR_W1 + k] = lo;
    }
    // ---- fill W2 [64n][32k] hi/lo ----
    for (int e = tid; e < 2048; e += 256) {
        int n = e >> 5, k = e & 31;
        float wv = (n < 32) ? Ws[n*32 + k] : Wr[(n-32)*32 + k];
        __nv_bfloat16 hi = __float2bfloat16_rn(wv);
        __nv_bfloat16 lo = __float2bfloat16_rn(wv - __bfloat162float(hi));
        sW2hi[n*STR_W2 + k] = hi;
        sW2lo[n*STR_W2 + k] = lo;
    }
    if (tid < 32) {
        sBias[tid]    = bfp[tid];
        sBias[32+tid] = bgp[tid];
        sBias[64+tid] = bsp[tid];
        sBias[96+tid] = brp[tid];
    }
    // ---- fill A [128t][64k] hi/lo (k<32: tap t-dil, k>=32: tap t) ----
    for (int e = tid; e < 4096; e += 256) {
        int k2 = e >> 7, t = e & 127;       // k2 = k/2
        int k = k2 * 2;
        int c0 = k & 31;
        int tap = k >> 5;
        int tsrc = t0 + t - (tap ? 0 : dil);
        float v0 = 0.f, v1 = 0.f;
        if (tsrc >= 0 && tsrc < Ll) {
            v0 = hb[(size_t)c0*Ll + tsrc];
            v1 = hb[(size_t)(c0+1)*Ll + tsrc];
        }
        __nv_bfloat16 h0 = __float2bfloat16_rn(v0);
        __nv_bfloat16 h1 = __float2bfloat16_rn(v1);
        __nv_bfloat16 l0 = __float2bfloat16_rn(v0 - __bfloat162float(h0));
        __nv_bfloat16 l1 = __float2bfloat16_rn(v1 - __bfloat162float(h1));
        *(__nv_bfloat162*)(sAhi + t*STR_A + k) = __nv_bfloat162(h0, h1);
        *(__nv_bfloat162*)(sAlo + t*STR_A + k) = __nv_bfloat162(l0, l1);
    }
    __syncthreads();

    const int w    = tid >> 5;
    const int lane = tid & 31;
    const int r0   = lane >> 2;
    const int tig  = lane & 3;
    const int mrow = w * 16;

    // ---- GEMM1: D[128,64] = A[128,64] x W1^T ----
    float d[8][4];
    #pragma unroll
    for (int n = 0; n < 8; ++n)
        #pragma unroll
        for (int j = 0; j < 4; ++j) d[n][j] = 0.f;

    #pragma unroll
    for (int kt = 0; kt < 4; ++kt) {
        const __nv_bfloat16* pa = sAhi + (mrow + r0)*STR_A + kt*16 + tig*2;
        const __nv_bfloat16* pl = sAlo + (mrow + r0)*STR_A + kt*16 + tig*2;
        uint32_t ah[4], al[4];
        ah[0] = ld32(pa);              ah[1] = ld32(pa + 8*STR_A);
        ah[2] = ld32(pa + 8);          ah[3] = ld32(pa + 8*STR_A + 8);
        al[0] = ld32(pl);              al[1] = ld32(pl + 8*STR_A);
        al[2] = ld32(pl + 8);          al[3] = ld32(pl + 8*STR_A + 8);
        #pragma unroll
        for (int n = 0; n < 8; ++n) {
            const __nv_bfloat16* pb = sW1hi + (n*8 + r0)*STR_W1 + kt*16 + tig*2;
            const __nv_bfloat16* pq = sW1lo + (n*8 + r0)*STR_W1 + kt*16 + tig*2;
            uint32_t bh[2] = { ld32(pb), ld32(pb + 8) };
            uint32_t bl[2] = { ld32(pq), ld32(pq + 8) };
            mma_bf16(d[n], ah, bh);
            mma_bf16(d[n], ah, bl);
            mma_bf16(d[n], al, bh);
        }
    }

    // ---- epilogue 1: o = tanh(f+bf)*sig(g+bg) -> sO hi/lo ----
    #pragma unroll
    for (int n = 0; n < 4; ++n) {
        int c = n*8 + tig*2;
        float f0 = d[n][0] + sBias[c],      f1 = d[n][1] + sBias[c+1];
        float f2 = d[n][2] + sBias[c],      f3 = d[n][3] + sBias[c+1];
        float gg0 = d[n+4][0] + sBias[32+c], gg1 = d[n+4][1] + sBias[32+c+1];
        float gg2 = d[n+4][2] + sBias[32+c], gg3 = d[n+4][3] + sBias[32+c+1];
        float o0 = ftanh(f0)*fsig(gg0), o1 = ftanh(f1)*fsig(gg1);
        float o2 = ftanh(f2)*fsig(gg2), o3 = ftanh(f3)*fsig(gg3);
        __nv_bfloat16 h0 = __float2bfloat16_rn(o0), h1 = __float2bfloat16_rn(o1);
        __nv_bfloat16 h2 = __float2bfloat16_rn(o2), h3 = __float2bfloat16_rn(o3);
        __nv_bfloat16 l0 = __float2bfloat16_rn(o0 - __bfloat162float(h0));
        __nv_bfloat16 l1 = __float2bfloat16_rn(o1 - __bfloat162float(h1));
        __nv_bfloat16 l2 = __float2bfloat16_rn(o2 - __bfloat162float(h2));
        __nv_bfloat16 l3 = __float2bfloat16_rn(o3 - __bfloat162float(h3));
        *(__nv_bfloat162*)(sOhi + (mrow+r0  )*STR_O + c) = __nv_bfloat162(h0, h1);
        *(__nv_bfloat162*)(sOhi + (mrow+r0+8)*STR_O + c) = __nv_bfloat162(h2, h3);
        *(__nv_bfloat162*)(sOlo + (mrow+r0  )*STR_O + c) = __nv_bfloat162(l0, l1);
        *(__nv_bfloat162*)(sOlo + (mrow+r0+8)*STR_O + c) = __nv_bfloat162(l2, l3);
    }
    __syncthreads();

    // ---- GEMM2: E[128,64] = O[128,32] x W2^T ----
    float e2[8][4];
    #pragma unroll
    for (int n = 0; n < 8; ++n)
        #pragma unroll
        for (int j = 0; j < 4; ++j) e2[n][j] = 0.f;

    #pragma unroll
    for (int kt = 0; kt < 2; ++kt) {
        const __nv_bfloat16* pa = sOhi + (mrow + r0)*STR_O + kt*16 + tig*2;
        const __nv_bfloat16* pl = sOlo + (mrow + r0)*STR_O + kt*16 + tig*2;
        uint32_t ah[4], al[4];
        ah[0] = ld32(pa);              ah[1] = ld32(pa + 8*STR_O);
        ah[2] = ld32(pa + 8);          ah[3] = ld32(pa + 8*STR_O + 8);
        al[0] = ld32(pl);              al[1] = ld32(pl + 8*STR_O);
        al[2] = ld32(pl + 8);          al[3] = ld32(pl + 8*STR_O + 8);
        #pragma unroll
        for (int n = 0; n < 8; ++n) {
            const __nv_bfloat16* pb = sW2hi + (n*8 + r0)*STR_W2 + kt*16 + tig*2;
            const __nv_bfloat16* pq = sW2lo + (n*8 + r0)*STR_W2 + kt*16 + tig*2;
            uint32_t bh[2] = { ld32(pb), ld32(pb + 8) };
            uint32_t bl[2] = { ld32(pq), ld32(pq + 8) };
            mma_bf16(e2[n], ah, bh);
            mma_bf16(e2[n], ah, bl);
            mma_bf16(e2[n], al, bh);
        }
    }
    __syncthreads();   // all warps done reading sO before sS2 alias write

    // ---- stage s (n 0..3) and r (n 4..7) to f32 SMEM for coalesced output ----
    #pragma unroll
    for (int n = 0; n < 4; ++n) {
        int c = n*8 + tig*2;
        sS [(mrow+r0  )*STR_S + c]   = e2[n][0];
        sS [(mrow+r0  )*STR_S + c+1] = e2[n][1];
        sS [(mrow+r0+8)*STR_S + c]   = e2[n][2];
        sS [(mrow+r0+8)*STR_S + c+1] = e2[n][3];
        sS2[(mrow+r0  )*STR_S + c]   = e2[n+4][0];
        sS2[(mrow+r0  )*STR_S + c+1] = e2[n+4][1];
        sS2[(mrow+r0+8)*STR_S + c]   = e2[n+4][2];
        sS2[(mrow+r0+8)*STR_S + c+1] = e2[n+4][3];
    }
    __syncthreads();

    // ---- writeout: skip (+)= s+bs ; h_out = h_in + r+br ----
    for (int e = tid; e < 4096; e += 256) {
        int c = e >> 7, t = e & 127;
        int gt = t0 + t;
        if (gt < Ll) {
            size_t idx = (size_t)(b*Cc + c)*Ll + gt;
            float sv = sS[t*STR_S + c] + sBias[64 + c];
            g_skip[idx] = FIRST ? sv : (g_skip[idx] + sv);
            float rv = sS2[t*STR_S + c] + sBias[96 + c];
            h_out[idx] = hb[(size_t)c*Ll + gt] + rv;
        }
    }
}

// ---------------- downsample conv: skip[B,32,L] -> y[B,64,22500] ----------------
__global__ void __launch_bounds__(256, 2)
downsample_kernel(const float* __restrict__ wd, const float* __restrict__ bd)
{
    extern __shared__ float smem[];
    float4* sWd = (float4*)smem;
    float*  sSk = smem + 8192;

    int tid = threadIdx.x;
    int b   = blockIdx.y;
    int u0  = blockIdx.x * 64;
    int t0  = u0 * 4;

    const float4* wd4 = (const float4*)wd;
    for (int e = tid; e < 2048; e += 256) sWd[e] = wd4[e];

    const float* skb = g_skip + (size_t)b * Cc * Ll;
    for (int e = tid; e < 32*256; e += 256) {
        int c = e >> 8, j = e & 255;
        int gt = t0 + j;
        sSk[c*256 + j] = (gt < Ll) ? skb[c*Ll + gt] : 0.0f;
    }
    __syncthreads();

    int op = tid >> 3;
    int o0 = op, o1 = op + 32;
    int qq = tid & 7;
    float a0[8], a1[8];
    float bd0 = bd[o0], bd1 = bd[o1];
    #pragma unroll
    for (int i = 0; i < 8; ++i) { a0[i]=bd0; a1[i]=bd1; }

    #pragma unroll 4
    for (int c = 0; c < 32; ++c) {
        float4 w0v = sWd[o0*32 + c];
        float4 w1v = sWd[o1*32 + c];
        const float* sr = sSk + c*256;
        #pragma unroll
        for (int i = 0; i < 8; ++i) {
            float4 sv = *(const float4*)(sr + (i*8 + qq)*4);
            a0[i] += w0v.x*sv.x + w0v.y*sv.y + w0v.z*sv.z + w0v.w*sv.w;
            a1[i] += w1v.x*sv.x + w1v.y*sv.y + w1v.z*sv.z + w1v.w*sv.w;
        }
    }
    float* yb = g_y + (size_t)b * FLATN;
    #pragma unroll
    for (int i = 0; i < 8; ++i) {
        int u = u0 + i*8 + qq;
        if (u < DOWNL) {
            yb[o0*DOWNL + u] = a0[i];
            yb[o1*DOWNL + u] = a1[i];
        }
    }
}

// ---------------- FC ----------------
__global__ void zero_o_kernel() {
    int i = threadIdx.x;
    if (i < Bb*64) g_o[i] = 0.0f;
}

#define FC_CHUNK 2000
__global__ void __launch_bounds__(512, 2)
fc_kernel(const float* __restrict__ fcW)
{
    extern __shared__ float smem[];
    int tid = threadIdx.x;
    int f0  = blockIdx.x * FC_CHUNK;
    int mg  = blockIdx.y;

    for (int e = tid; e < 8*FC_CHUNK/4; e += 512) {
        int b = e / (FC_CHUNK/4), f4 = e - b*(FC_CHUNK/4);
        ((float4*)smem)[b*(FC_CHUNK/4) + f4] =
            *(const float4*)(g_y + (size_t)b*FLATN + f0 + f4*4);
    }
    __syncthreads();

    int w = tid >> 5, lane = tid & 31;
    int m0 = mg*32 + w;
    float acc0[8], acc1[8];
    #pragma unroll
    for (int b = 0; b < 8; ++b) { acc0[b]=0.f; acc1[b]=0.f; }

    const float4* W0 = (const float4*)(fcW + (size_t)m0      * FLATN + f0);
    const float4* W1 = (const float4*)(fcW + (size_t)(m0+16) * FLATN + f0);
    for (int i4 = lane; i4 < FC_CHUNK/4; i4 += 32) {
        float4 wv0 = __ldg(W0 + i4);
        float4 wv1 = __ldg(W1 + i4);
        #pragma unroll
        for (int b = 0; b < 8; ++b) {
            float4 yv = ((const float4*)smem)[b*(FC_CHUNK/4) + i4];
            acc0[b] += wv0.x*yv.x + wv0.y*yv.y + wv0.z*yv.z + wv0.w*yv.w;
            acc1[b] += wv1.x*yv.x + wv1.y*yv.y + wv1.z*yv.z + wv1.w*yv.w;
        }
    }
    #pragma unroll
    for (int off = 16; off; off >>= 1) {
        #pragma unroll
        for (int b = 0; b < 8; ++b) {
            acc0[b] += __shfl_xor_sync(0xFFFFFFFFu, acc0[b], off);
            acc1[b] += __shfl_xor_sync(0xFFFFFFFFu, acc1[b], off);
        }
    }
    if (lane == 0) {
        #pragma unroll
        for (int b = 0; b < 8; ++b) {
            atomicAdd(&g_o[b*64 + m0],      acc0[b]);
            atomicAdd(&g_o[b*64 + m0 + 16], acc1[b]);
        }
    }
}

// ---------------- final ----------------
__global__ void final_kernel(const float* __restrict__ eps,
                             const float* __restrict__ fcb,
                             float* __restrict__ out)
{
    int i = threadIdx.x;
    int b = i >> 5, l = i & 31;
    float mu = g_o[b*64 + l]      + fcb[l];
    float lv = g_o[b*64 + 32 + l] + fcb[32 + l];
    float z  = mu + eps[b*32 + l] * expf(0.5f * lv);
    out[i]       = mu;
    out[256 + i] = lv;
    out[512 + i] = z;
}

// ---------------- launch ----------------
extern "C" void kernel_launch(void* const* d_in, const int* in_sizes, int n_in,
                              void* d_out, int out_size)
{
    (void)in_sizes; (void)n_in; (void)out_size;
    const float* x   = (const float*)d_in[0];
    const float* eps = (const float*)d_in[1];
    const float* w0  = (const float*)d_in[2];
    const float* b0  = (const float*)d_in[3];
    const float* Wf  = (const float*)d_in[4];
    const float* bf  = (const float*)d_in[5];
    const float* Wg  = (const float*)d_in[6];
    const float* bg  = (const float*)d_in[7];
    const float* Ws  = (const float*)d_in[8];
    const float* bs  = (const float*)d_in[9];
    const float* Wr  = (const float*)d_in[10];
    const float* br  = (const float*)d_in[11];
    const float* wd  = (const float*)d_in[12];
    const float* bd  = (const float*)d_in[13];
    const float* fcW = (const float*)d_in[14];
    const float* fcb = (const float*)d_in[15];
    float* out = (float*)d_out;

    cudaFuncSetAttribute(wn_block_mma<true>,  cudaFuncAttributeMaxDynamicSharedMemorySize, SMEM_BLK);
    cudaFuncSetAttribute(wn_block_mma<false>, cudaFuncAttributeMaxDynamicSharedMemorySize, SMEM_BLK);
    cudaFuncSetAttribute(downsample_kernel,   cudaFuncAttributeMaxDynamicSharedMemorySize, 65536);
    cudaFuncSetAttribute(fc_kernel,           cudaFuncAttributeMaxDynamicSharedMemorySize, 8*FC_CHUNK*4);

    conv0_kernel<<<dim3((Ll + 255)/256, Bb*Cc), 256>>>(x, w0, b0);

    dim3 bgrid(704, Bb);   // 704*128 = 90112 >= 90000
    for (int i = 0; i < 6; ++i) {
        int dil = 1 << i;
        int ping = i & 1;
        const float* wfp = Wf + i*2048; const float* wgp = Wg + i*2048;
        const float* wsp = Ws + i*1024; const float* wrp = Wr + i*1024;
        const float* bfi = bf + i*32;   const float* bgi = bg + i*32;
        const float* bsi = bs + i*32;   const float* bri = br + i*32;
        if (i == 0)
            wn_block_mma<true ><<<bgrid, 256, SMEM_BLK>>>(ping, dil, wfp, wgp, wsp, wrp, bfi, bgi, bsi, bri);
        else
            wn_block_mma<false><<<bgrid, 256, SMEM_BLK>>>(ping, dil, wfp, wgp, wsp, wrp, bfi, bgi, bsi, bri);
    }

    downsample_kernel<<<dim3((DOWNL + 63)/64, Bb), 256, 65536>>>(wd, bd);
    zero_o_kernel<<<1, 512>>>();
    fc_kernel<<<dim3(FLATN/FC_CHUNK, 2), 512, 8*FC_CHUNK*4>>>(fcW);
    final_kernel<<<1, 256>>>(eps, fcb, out);
}

// round 6
// speedup vs baseline: 1.6476x; 1.6476x over previous
#include <cuda_runtime.h>
#include <cuda_bf16.h>
#include <cstdint>
#include <math.h>

#define Bb   8
#define Cc   32
#define Ll   90000
#define DOWNL 22500
#define FLATN 1440000

// ---- scratch ----
__device__ float g_hA[Bb*Cc*Ll];
__device__ float g_hB[Bb*Cc*Ll];
__device__ float g_skip[Bb*Cc*Ll];
__device__ float g_y[Bb*FLATN];
__device__ float g_o[Bb*64];

__device__ __forceinline__ float fsig(float x)  { return 1.0f / (1.0f + __expf(-x)); }
__device__ __forceinline__ float ftanh(float x) { return 2.0f * fsig(2.0f * x) - 1.0f; }

__device__ __forceinline__ void mma_bf16(float d[4], const uint32_t a[4], const uint32_t b[2]) {
    asm volatile(
        "mma.sync.aligned.m16n8k16.row.col.f32.bf16.bf16.f32 "
        "{%0,%1,%2,%3}, {%4,%5,%6,%7}, {%8,%9}, {%0,%1,%2,%3};"
        : "+f"(d[0]), "+f"(d[1]), "+f"(d[2]), "+f"(d[3])
        : "r"(a[0]), "r"(a[1]), "r"(a[2]), "r"(a[3]), "r"(b[0]), "r"(b[1]));
}
__device__ __forceinline__ uint32_t ld32s(const __nv_bfloat16* p) {
    return *(const uint32_t*)p;
}
__device__ __forceinline__ uint32_t pack_hi(float a, float b, uint32_t& lo) {
    __nv_bfloat16 ha = __float2bfloat16_rn(a);
    __nv_bfloat16 hb = __float2bfloat16_rn(b);
    __nv_bfloat16 la = __float2bfloat16_rn(a - __bfloat162float(ha));
    __nv_bfloat16 lb = __float2bfloat16_rn(b - __bfloat162float(hb));
    __nv_bfloat162 h2(ha, hb), l2(la, lb);
    lo = *(uint32_t*)&l2;
    return *(uint32_t*)&h2;
}

// SMEM strides (bf16 elements) — conflict-free fragment access (verified bank math)
#define STR_W1 72
#define STR_W2 40

#define OFF_W1HI  0
#define OFF_W1LO  9216
#define OFF_W2HI  18432
#define OFF_W2LO  23552
#define OFF_BIAS  28672
#define SMEM_BLK  29184

#define TILES_PER_CTA 4

// ---------------- conv0 ----------------
__global__ void conv0_kernel(const float* __restrict__ x,
                             const float* __restrict__ w0,
                             const float* __restrict__ b0)
{
    int t  = blockIdx.x * blockDim.x + threadIdx.x;
    int bc = blockIdx.y;
    if (t >= Ll) return;
    int b = bc >> 5, c = bc & 31;
    const float* xb = x + b * Ll;
    float wk0 = w0[c*3+0], wk1 = w0[c*3+1], wk2 = w0[c*3+2];
    float v = wk2 * xb[t] + b0[c];
    if (t >= 1) v += wk1 * xb[t-1];
    if (t >= 2) v += wk0 * xb[t-2];
    g_hA[(b*Cc + c)*Ll + t] = v;
}

// ---------------- WaveNet block: mma.sync bf16, registers-only dataflow ----------------
template<bool FIRST>
__global__ void __launch_bounds__(256, 2)
wn_block_mma(int ping, int dil,
             const float* __restrict__ Wf, const float* __restrict__ Wg,
             const float* __restrict__ Ws, const float* __restrict__ Wr,
             const float* __restrict__ bfp, const float* __restrict__ bgp,
             const float* __restrict__ bsp, const float* __restrict__ brp)
{
    extern __shared__ char sm[];
    __nv_bfloat16* sW1hi = (__nv_bfloat16*)(sm + OFF_W1HI);
    __nv_bfloat16* sW1lo = (__nv_bfloat16*)(sm + OFF_W1LO);
    __nv_bfloat16* sW2hi = (__nv_bfloat16*)(sm + OFF_W2HI);
    __nv_bfloat16* sW2lo = (__nv_bfloat16*)(sm + OFF_W2LO);
    float* sBias = (float*)(sm + OFF_BIAS);

    const float* h_in  = ping ? g_hB : g_hA;
    float*       h_out = ping ? g_hA : g_hB;

    const int tid = threadIdx.x;
    const int b   = blockIdx.y;
    const float* hb = h_in + (size_t)b * Cc * Ll;

    // ---- weights (once per CTA) ----
    for (int e = tid; e < 4096; e += 256) {
        int n = e >> 6, k = e & 63;
        float wv = (n < 32)
            ? ((k < 32) ? Wf[n*64 + k*2 + 0] : Wf[n*64 + (k-32)*2 + 1])
            : ((k < 32) ? Wg[(n-32)*64 + k*2 + 0] : Wg[(n-32)*64 + (k-32)*2 + 1]);
        __nv_bfloat16 hi = __float2bfloat16_rn(wv);
        sW1hi[n*STR_W1 + k] = hi;
        sW1lo[n*STR_W1 + k] = __float2bfloat16_rn(wv - __bfloat162float(hi));
    }
    for (int e = tid; e < 2048; e += 256) {
        int n = e >> 5, k = e & 31;
        float wv = (n < 32) ? Ws[n*32 + k] : Wr[(n-32)*32 + k];
        __nv_bfloat16 hi = __float2bfloat16_rn(wv);
        sW2hi[n*STR_W2 + k] = hi;
        sW2lo[n*STR_W2 + k] = __float2bfloat16_rn(wv - __bfloat162float(hi));
    }
    if (tid < 32) {
        sBias[tid]    = bfp[tid];
        sBias[32+tid] = bgp[tid];
        sBias[64+tid] = bsp[tid];
        sBias[96+tid] = brp[tid];
    }
    __syncthreads();

    const int w    = tid >> 5;
    const int lane = tid & 31;
    const int r0   = lane >> 2;
    const int tig  = lane & 3;
    const int mrow = w * 16;

    for (int it = 0; it < TILES_PER_CTA; ++it) {
        const int t0    = (blockIdx.x * TILES_PER_CTA + it) * 128;
        const int trow0 = t0 + mrow + r0;

        // ---- A fragments direct from global (hi/lo split in regs) ----
        // frag reg map: a[kt][(p&1)*2 + half]; kt 0,1 = tap(t-dil), kt 2,3 = tap(t)
        uint32_t ah[4][4], al[4][4];
        #pragma unroll
        for (int half = 0; half < 2; ++half) {
            const int r  = trow0 + half*8;
            const int tA = r - dil;
            const bool okA = (tA >= 0) && (tA < Ll);
            const bool okB = (r < Ll);
            #pragma unroll
            for (int p = 0; p < 4; ++p) {
                const int c0 = p*8 + tig*2;
                float vA0 = okA ? __ldg(hb + (size_t)c0*Ll + tA)     : 0.f;
                float vA1 = okA ? __ldg(hb + (size_t)(c0+1)*Ll + tA) : 0.f;
                float vB0 = okB ? __ldg(hb + (size_t)c0*Ll + r)      : 0.f;
                float vB1 = okB ? __ldg(hb + (size_t)(c0+1)*Ll + r)  : 0.f;
                const int ri = (p & 1)*2 + half;
                ah[p>>1][ri]       = pack_hi(vA0, vA1, al[p>>1][ri]);
                ah[2 + (p>>1)][ri] = pack_hi(vB0, vB1, al[2 + (p>>1)][ri]);
            }
        }

        // ---- GEMM1: D[128,64] = A x W1^T  (3-term hi/lo split) ----
        float d[8][4];
        #pragma unroll
        for (int n = 0; n < 8; ++n)
            #pragma unroll
            for (int j = 0; j < 4; ++j) d[n][j] = 0.f;

        #pragma unroll
        for (int kt = 0; kt < 4; ++kt) {
            #pragma unroll
            for (int n = 0; n < 8; ++n) {
                const __nv_bfloat16* pb = sW1hi + (n*8 + r0)*STR_W1 + kt*16 + tig*2;
                const __nv_bfloat16* pq = sW1lo + (n*8 + r0)*STR_W1 + kt*16 + tig*2;
                uint32_t bh[2] = { ld32s(pb), ld32s(pb + 8) };
                uint32_t bl[2] = { ld32s(pq), ld32s(pq + 8) };
                mma_bf16(d[n], ah[kt], bh);
                mma_bf16(d[n], ah[kt], bl);
                mma_bf16(d[n], al[kt], bh);
            }
        }

        // ---- epilogue 1 in registers: o = tanh(f+bf)*sig(g+bg) -> GEMM2 A-frags ----
        uint32_t a2h[2][4], a2l[2][4];
        #pragma unroll
        for (int nn = 0; nn < 4; ++nn) {
            const int c = nn*8 + tig*2;
            const float b0f = sBias[c],      b1f = sBias[c+1];
            const float b0g = sBias[32+c],   b1g = sBias[32+c+1];
            float o0 = ftanh(d[nn][0] + b0f) * fsig(d[nn+4][0] + b0g);
            float o1 = ftanh(d[nn][1] + b1f) * fsig(d[nn+4][1] + b1g);
            float o2 = ftanh(d[nn][2] + b0f) * fsig(d[nn+4][2] + b0g);
            float o3 = ftanh(d[nn][3] + b1f) * fsig(d[nn+4][3] + b1g);
            const int kt2 = nn >> 1;
            const int ri  = (nn & 1)*2;
            a2h[kt2][ri]     = pack_hi(o0, o1, a2l[kt2][ri]);
            a2h[kt2][ri + 1] = pack_hi(o2, o3, a2l[kt2][ri + 1]);
        }

        // ---- GEMM2: E[128,64] = O[128,32] x W2^T ----
        float e2[8][4];
        #pragma unroll
        for (int n = 0; n < 8; ++n)
            #pragma unroll
            for (int j = 0; j < 4; ++j) e2[n][j] = 0.f;

        #pragma unroll
        for (int kt = 0; kt < 2; ++kt) {
            #pragma unroll
            for (int n = 0; n < 8; ++n) {
                const __nv_bfloat16* pb = sW2hi + (n*8 + r0)*STR_W2 + kt*16 + tig*2;
                const __nv_bfloat16* pq = sW2lo + (n*8 + r0)*STR_W2 + kt*16 + tig*2;
                uint32_t bh[2] = { ld32s(pb), ld32s(pb + 8) };
                uint32_t bl[2] = { ld32s(pq), ld32s(pq + 8) };
                mma_bf16(e2[n], a2h[kt], bh);
                mma_bf16(e2[n], a2h[kt], bl);
                mma_bf16(e2[n], a2l[kt], bh);
            }
        }

        // ---- writeout from D-fragment layout (32B-coalesced segments) ----
        #pragma unroll
        for (int n = 0; n < 4; ++n) {
            #pragma unroll
            for (int j = 0; j < 4; ++j) {
                const int cc  = n*8 + tig*2 + (j & 1);
                const int row = trow0 + ((j >> 1) << 3);
                if (row < Ll) {
                    const size_t idx = (size_t)(b*Cc + cc)*Ll + row;
                    const float sv = e2[n][j] + sBias[64 + cc];
                    g_skip[idx] = FIRST ? sv : (g_skip[idx] + sv);
                    const float rv = e2[n+4][j] + sBias[96 + cc];
                    h_out[idx] = hb[(size_t)cc*Ll + row] + rv;
                }
            }
        }
    }
}

// ---------------- downsample conv ----------------
__global__ void __launch_bounds__(256, 2)
downsample_kernel(const float* __restrict__ wd, const float* __restrict__ bd)
{
    extern __shared__ float smem[];
    float4* sWd = (float4*)smem;
    float*  sSk = smem + 8192;

    int tid = threadIdx.x;
    int b   = blockIdx.y;
    int u0  = blockIdx.x * 64;
    int t0  = u0 * 4;

    const float4* wd4 = (const float4*)wd;
    for (int e = tid; e < 2048; e += 256) sWd[e] = wd4[e];

    const float* skb = g_skip + (size_t)b * Cc * Ll;
    for (int e = tid; e < 32*256; e += 256) {
        int c = e >> 8, j = e & 255;
        int gt = t0 + j;
        sSk[c*256 + j] = (gt < Ll) ? skb[c*Ll + gt] : 0.0f;
    }
    __syncthreads();

    int op = tid >> 3;
    int o0 = op, o1 = op + 32;
    int qq = tid & 7;
    float a0[8], a1[8];
    float bd0 = bd[o0], bd1 = bd[o1];
    #pragma unroll
    for (int i = 0; i < 8; ++i) { a0[i]=bd0; a1[i]=bd1; }

    #pragma unroll 4
    for (int c = 0; c < 32; ++c) {
        float4 w0v = sWd[o0*32 + c];
        float4 w1v = sWd[o1*32 + c];
        const float* sr = sSk + c*256;
        #pragma unroll
        for (int i = 0; i < 8; ++i) {
            float4 sv = *(const float4*)(sr + (i*8 + qq)*4);
            a0[i] += w0v.x*sv.x + w0v.y*sv.y + w0v.z*sv.z + w0v.w*sv.w;
            a1[i] += w1v.x*sv.x + w1v.y*sv.y + w1v.z*sv.z + w1v.w*sv.w;
        }
    }
    float* yb = g_y + (size_t)b * FLATN;
    #pragma unroll
    for (int i = 0; i < 8; ++i) {
        int u = u0 + i*8 + qq;
        if (u < DOWNL) {
            yb[o0*DOWNL + u] = a0[i];
            yb[o1*DOWNL + u] = a1[i];
        }
    }
}

// ---------------- FC ----------------
__global__ void zero_o_kernel() {
    int i = threadIdx.x;
    if (i < Bb*64) g_o[i] = 0.0f;
}

#define FC_CHUNK 2000
__global__ void __launch_bounds__(512, 2)
fc_kernel(const float* __restrict__ fcW)
{
    extern __shared__ float smem[];
    int tid = threadIdx.x;
    int f0  = blockIdx.x * FC_CHUNK;
    int mg  = blockIdx.y;

    for (int e = tid; e < 8*FC_CHUNK/4; e += 512) {
        int b = e / (FC_CHUNK/4), f4 = e - b*(FC_CHUNK/4);
        ((float4*)smem)[b*(FC_CHUNK/4) + f4] =
            *(const float4*)(g_y + (size_t)b*FLATN + f0 + f4*4);
    }
    __syncthreads();

    int w = tid >> 5, lane = tid & 31;
    int m0 = mg*32 + w;
    float acc0[8], acc1[8];
    #pragma unroll
    for (int b = 0; b < 8; ++b) { acc0[b]=0.f; acc1[b]=0.f; }

    const float4* W0 = (const float4*)(fcW + (size_t)m0      * FLATN + f0);
    const float4* W1 = (const float4*)(fcW + (size_t)(m0+16) * FLATN + f0);
    for (int i4 = lane; i4 < FC_CHUNK/4; i4 += 32) {
        float4 wv0 = __ldg(W0 + i4);
        float4 wv1 = __ldg(W1 + i4);
        #pragma unroll
        for (int b = 0; b < 8; ++b) {
            float4 yv = ((const float4*)smem)[b*(FC_CHUNK/4) + i4];
            acc0[b] += wv0.x*yv.x + wv0.y*yv.y + wv0.z*yv.z + wv0.w*yv.w;
            acc1[b] += wv1.x*yv.x + wv1.y*yv.y + wv1.z*yv.z + wv1.w*yv.w;
        }
    }
    #pragma unroll
    for (int off = 16; off; off >>= 1) {
        #pragma unroll
        for (int b = 0; b < 8; ++b) {
            acc0[b] += __shfl_xor_sync(0xFFFFFFFFu, acc0[b], off);
            acc1[b] += __shfl_xor_sync(0xFFFFFFFFu, acc1[b], off);
        }
    }
    if (lane == 0) {
        #pragma unroll
        for (int b = 0; b < 8; ++b) {
            atomicAdd(&g_o[b*64 + m0],      acc0[b]);
            atomicAdd(&g_o[b*64 + m0 + 16], acc1[b]);
        }
    }
}

// ---------------- final ----------------
__global__ void final_kernel(const float* __restrict__ eps,
                             const float* __restrict__ fcb,
                             float* __restrict__ out)
{
    int i = threadIdx.x;
    int b = i >> 5, l = i & 31;
    float mu = g_o[b*64 + l]      + fcb[l];
    float lv = g_o[b*64 + 32 + l] + fcb[32 + l];
    float z  = mu + eps[b*32 + l] * expf(0.5f * lv);
    out[i]       = mu;
    out[256 + i] = lv;
    out[512 + i] = z;
}

// ---------------- launch ----------------
extern "C" void kernel_launch(void* const* d_in, const int* in_sizes, int n_in,
                              void* d_out, int out_size)
{
    (void)in_sizes; (void)n_in; (void)out_size;
    const float* x   = (const float*)d_in[0];
    const float* eps = (const float*)d_in[1];
    const float* w0  = (const float*)d_in[2];
    const float* b0  = (const float*)d_in[3];
    const float* Wf  = (const float*)d_in[4];
    const float* bf  = (const float*)d_in[5];
    const float* Wg  = (const float*)d_in[6];
    const float* bg  = (const float*)d_in[7];
    const float* Ws  = (const float*)d_in[8];
    const float* bs  = (const float*)d_in[9];
    const float* Wr  = (const float*)d_in[10];
    const float* br  = (const float*)d_in[11];
    const float* wd  = (const float*)d_in[12];
    const float* bd  = (const float*)d_in[13];
    const float* fcW = (const float*)d_in[14];
    const float* fcb = (const float*)d_in[15];
    float* out = (float*)d_out;

    cudaFuncSetAttribute(wn_block_mma<true>,  cudaFuncAttributeMaxDynamicSharedMemorySize, SMEM_BLK);
    cudaFuncSetAttribute(wn_block_mma<false>, cudaFuncAttributeMaxDynamicSharedMemorySize, SMEM_BLK);
    cudaFuncSetAttribute(downsample_kernel,   cudaFuncAttributeMaxDynamicSharedMemorySize, 65536);
    cudaFuncSetAttribute(fc_kernel,           cudaFuncAttributeMaxDynamicSharedMemorySize, 8*FC_CHUNK*4);

    conv0_kernel<<<dim3((Ll + 255)/256, Bb*Cc), 256>>>(x, w0, b0);

    dim3 bgrid(704 / TILES_PER_CTA, Bb);   // 176 x 8 CTAs, 4 tiles each
    for (int i = 0; i < 6; ++i) {
        int dil = 1 << i;
        int ping = i & 1;
        const float* wfp = Wf + i*2048; const float* wgp = Wg + i*2048;
        const float* wsp = Ws + i*1024; const float* wrp = Wr + i*1024;
        const float* bfi = bf + i*32;   const float* bgi = bg + i*32;
        const float* bsi = bs + i*32;   const float* bri = br + i*32;
        if (i == 0)
            wn_block_mma<true ><<<bgrid, 256, SMEM_BLK>>>(ping, dil, wfp, wgp, wsp, wrp, bfi, bgi, bsi, bri);
        else
            wn_block_mma<false><<<bgrid, 256, SMEM_BLK>>>(ping, dil, wfp, wgp, wsp, wrp, bfi, bgi, bsi, bri);
    }

    downsample_kernel<<<dim3((DOWNL + 63)/64, Bb), 256, 65536>>>(wd, bd);
    zero_o_kernel<<<1, 512>>>();
    fc_kernel<<<dim3(FLATN/FC_CHUNK, 2), 512, 8*FC_CHUNK*4>>>(fcW);
    final_kernel<<<1, 256>>>(eps, fcb, out);
}

// round 7
// speedup vs baseline: 2.3099x; 1.4019x over previous
#include <cuda_runtime.h>
#include <cuda_bf16.h>
#include <cstdint>
#include <math.h>

#define Bb   8
#define Cc   32
#define Ll   90000
#define DOWNL 22500
#define FLATN 1440000

// ---- scratch ----
__device__ float g_hA[Bb*Cc*Ll];
__device__ float g_hB[Bb*Cc*Ll];
__device__ float g_skip[Bb*Cc*Ll];
__device__ float g_y[Bb*FLATN];
__device__ float g_o[Bb*64];

__device__ __forceinline__ float fsig(float x)  { return 1.0f / (1.0f + __expf(-x)); }
__device__ __forceinline__ float ftanh(float x) { return 2.0f * fsig(2.0f * x) - 1.0f; }

__device__ __forceinline__ void mma_bf16(float d[4], const uint32_t a[4], const uint32_t b[2]) {
    asm volatile(
        "mma.sync.aligned.m16n8k16.row.col.f32.bf16.bf16.f32 "
        "{%0,%1,%2,%3}, {%4,%5,%6,%7}, {%8,%9}, {%0,%1,%2,%3};"
        : "+f"(d[0]), "+f"(d[1]), "+f"(d[2]), "+f"(d[3])
        : "r"(a[0]), "r"(a[1]), "r"(a[2]), "r"(a[3]), "r"(b[0]), "r"(b[1]));
}
__device__ __forceinline__ uint32_t ld32s(const __nv_bfloat16* p) {
    return *(const uint32_t*)p;
}
__device__ __forceinline__ uint32_t pack_hi(float a, float b, uint32_t& lo) {
    __nv_bfloat16 ha = __float2bfloat16_rn(a);
    __nv_bfloat16 hb = __float2bfloat16_rn(b);
    __nv_bfloat16 la = __float2bfloat16_rn(a - __bfloat162float(ha));
    __nv_bfloat16 lb = __float2bfloat16_rn(b - __bfloat162float(hb));
    __nv_bfloat162 h2(ha, hb), l2(la, lb);
    lo = *(uint32_t*)&l2;
    return *(uint32_t*)&h2;
}
// reconstruct (v0, v1) from hi/lo packed bf16x2
__device__ __forceinline__ float2 bf2sum(uint32_t h, uint32_t l) {
    __nv_bfloat162 hh = *(__nv_bfloat162*)&h;
    __nv_bfloat162 ll = *(__nv_bfloat162*)&l;
    return make_float2(__bfloat162float(hh.x) + __bfloat162float(ll.x),
                       __bfloat162float(hh.y) + __bfloat162float(ll.y));
}

#define STR_W1 72
#define STR_W2 40

#define OFF_W1HI  0
#define OFF_W1LO  9216
#define OFF_W2HI  18432
#define OFF_W2LO  23552
#define OFF_BIAS  28672
#define SMEM_BLK  29184

#define TILES_PER_CTA 4

// Load A fragments for a tile directly from global.
// aD = dilated tap (t-dil), aT = current tap (t); each [2 kt][4 ri].
__device__ __forceinline__ void load_A(const float* __restrict__ hb,
                                       int trow0, int dil, int tig,
                                       uint32_t (&aDh)[2][4], uint32_t (&aDl)[2][4],
                                       uint32_t (&aTh)[2][4], uint32_t (&aTl)[2][4])
{
    #pragma unroll
    for (int half = 0; half < 2; ++half) {
        const int r  = trow0 + half*8;
        const int tA = r - dil;
        const bool okA = (tA >= 0) && (tA < Ll);
        const bool okB = (r < Ll);
        #pragma unroll
        for (int p = 0; p < 4; ++p) {
            const int c0 = p*8 + tig*2;
            float vA0 = okA ? __ldg(hb + (size_t)c0*Ll + tA)     : 0.f;
            float vA1 = okA ? __ldg(hb + (size_t)(c0+1)*Ll + tA) : 0.f;
            float vB0 = okB ? __ldg(hb + (size_t)c0*Ll + r)      : 0.f;
            float vB1 = okB ? __ldg(hb + (size_t)(c0+1)*Ll + r)  : 0.f;
            const int ri = (p & 1)*2 + half;
            aDh[p>>1][ri] = pack_hi(vA0, vA1, aDl[p>>1][ri]);
            aTh[p>>1][ri] = pack_hi(vB0, vB1, aTl[p>>1][ri]);
        }
    }
}

// ---------------- conv0 ----------------
__global__ void conv0_kernel(const float* __restrict__ x,
                             const float* __restrict__ w0,
                             const float* __restrict__ b0)
{
    int t  = blockIdx.x * blockDim.x + threadIdx.x;
    int bc = blockIdx.y;
    if (t >= Ll) return;
    int b = bc >> 5, c = bc & 31;
    const float* xb = x + b * Ll;
    float wk0 = w0[c*3+0], wk1 = w0[c*3+1], wk2 = w0[c*3+2];
    float v = wk2 * xb[t] + b0[c];
    if (t >= 1) v += wk1 * xb[t-1];
    if (t >= 2) v += wk0 * xb[t-2];
    g_hA[(b*Cc + c)*Ll + t] = v;
}

// ---------------- WaveNet block: mma.sync bf16, pipelined registers-only dataflow ----
template<bool FIRST>
__global__ void __launch_bounds__(256, 2)
wn_block_mma(int ping, int dil,
             const float* __restrict__ Wf, const float* __restrict__ Wg,
             const float* __restrict__ Ws, const float* __restrict__ Wr,
             const float* __restrict__ bfp, const float* __restrict__ bgp,
             const float* __restrict__ bsp, const float* __restrict__ brp)
{
    extern __shared__ char sm[];
    __nv_bfloat16* sW1hi = (__nv_bfloat16*)(sm + OFF_W1HI);
    __nv_bfloat16* sW1lo = (__nv_bfloat16*)(sm + OFF_W1LO);
    __nv_bfloat16* sW2hi = (__nv_bfloat16*)(sm + OFF_W2HI);
    __nv_bfloat16* sW2lo = (__nv_bfloat16*)(sm + OFF_W2LO);
    float* sBias = (float*)(sm + OFF_BIAS);

    const float* h_in  = ping ? g_hB : g_hA;
    float*       h_out = ping ? g_hA : g_hB;

    const int tid = threadIdx.x;
    const int b   = blockIdx.y;
    const float* hb = h_in + (size_t)b * Cc * Ll;

    // ---- weights (once per CTA) ----
    for (int e = tid; e < 4096; e += 256) {
        int n = e >> 6, k = e & 63;
        float wv = (n < 32)
            ? ((k < 32) ? Wf[n*64 + k*2 + 0] : Wf[n*64 + (k-32)*2 + 1])
            : ((k < 32) ? Wg[(n-32)*64 + k*2 + 0] : Wg[(n-32)*64 + (k-32)*2 + 1]);
        __nv_bfloat16 hi = __float2bfloat16_rn(wv);
        sW1hi[n*STR_W1 + k] = hi;
        sW1lo[n*STR_W1 + k] = __float2bfloat16_rn(wv - __bfloat162float(hi));
    }
    for (int e = tid; e < 2048; e += 256) {
        int n = e >> 5, k = e & 31;
        float wv = (n < 32) ? Ws[n*32 + k] : Wr[(n-32)*32 + k];
        __nv_bfloat16 hi = __float2bfloat16_rn(wv);
        sW2hi[n*STR_W2 + k] = hi;
        sW2lo[n*STR_W2 + k] = __float2bfloat16_rn(wv - __bfloat162float(hi));
    }
    if (tid < 32) {
        sBias[tid]    = bfp[tid];
        sBias[32+tid] = bgp[tid];
        sBias[64+tid] = bsp[tid];
        sBias[96+tid] = brp[tid];
    }
    __syncthreads();

    const int w    = tid >> 5;
    const int lane = tid & 31;
    const int r0   = lane >> 2;
    const int tig  = lane & 3;
    const int mrow = w * 16;

    const int tileBase = blockIdx.x * TILES_PER_CTA;

    uint32_t aDh[2][4], aDl[2][4], aTh[2][4], aTl[2][4];
    load_A(hb, tileBase*128 + mrow + r0, dil, tig, aDh, aDl, aTh, aTl);

    #pragma unroll
    for (int it = 0; it < TILES_PER_CTA; ++it) {
        const int trow0 = (tileBase + it)*128 + mrow + r0;

        // ---- GEMM1: D[128,64] = A x W1^T (3-term hi/lo split) ----
        float acc[8][4];
        #pragma unroll
        for (int n = 0; n < 8; ++n)
            #pragma unroll
            for (int j = 0; j < 4; ++j) acc[n][j] = 0.f;

        #pragma unroll
        for (int kt = 0; kt < 2; ++kt) {
            #pragma unroll
            for (int n = 0; n < 8; ++n) {
                const __nv_bfloat16* pb = sW1hi + (n*8 + r0)*STR_W1 + kt*16 + tig*2;
                const __nv_bfloat16* pq = sW1lo + (n*8 + r0)*STR_W1 + kt*16 + tig*2;
                uint32_t bh[2] = { ld32s(pb), ld32s(pb + 8) };
                uint32_t bl[2] = { ld32s(pq), ld32s(pq + 8) };
                mma_bf16(acc[n], aDh[kt], bh);
                mma_bf16(acc[n], aDh[kt], bl);
                mma_bf16(acc[n], aDl[kt], bh);
            }
        }
        #pragma unroll
        for (int kt = 0; kt < 2; ++kt) {
            #pragma unroll
            for (int n = 0; n < 8; ++n) {
                const __nv_bfloat16* pb = sW1hi + (n*8 + r0)*STR_W1 + (2+kt)*16 + tig*2;
                const __nv_bfloat16* pq = sW1lo + (n*8 + r0)*STR_W1 + (2+kt)*16 + tig*2;
                uint32_t bh[2] = { ld32s(pb), ld32s(pb + 8) };
                uint32_t bl[2] = { ld32s(pq), ld32s(pq + 8) };
                mma_bf16(acc[n], aTh[kt], bh);
                mma_bf16(acc[n], aTh[kt], bl);
                mma_bf16(acc[n], aTl[kt], bh);
            }
        }

        // ---- epilogue 1: o = tanh(f+bf)*sig(g+bg) -> GEMM2 A-frags (registers) ----
        uint32_t a2h[2][4], a2l[2][4];
        #pragma unroll
        for (int nn = 0; nn < 4; ++nn) {
            const int c = nn*8 + tig*2;
            const float b0f = sBias[c],      b1f = sBias[c+1];
            const float b0g = sBias[32+c],   b1g = sBias[32+c+1];
            float o0 = ftanh(acc[nn][0] + b0f) * fsig(acc[nn+4][0] + b0g);
            float o1 = ftanh(acc[nn][1] + b1f) * fsig(acc[nn+4][1] + b1g);
            float o2 = ftanh(acc[nn][2] + b0f) * fsig(acc[nn+4][2] + b0g);
            float o3 = ftanh(acc[nn][3] + b1f) * fsig(acc[nn+4][3] + b1g);
            const int kt2 = nn >> 1;
            const int ri  = (nn & 1)*2;
            a2h[kt2][ri]     = pack_hi(o0, o1, a2l[kt2][ri]);
            a2h[kt2][ri + 1] = pack_hi(o2, o3, a2l[kt2][ri + 1]);
        }

        // ---- prefetch skip RMW values (hidden behind GEMM2) ----
        float skipv[4][4];
        if (!FIRST) {
            #pragma unroll
            for (int n = 0; n < 4; ++n) {
                #pragma unroll
                for (int j = 0; j < 4; ++j) {
                    const int cc  = n*8 + tig*2 + (j & 1);
                    const int row = trow0 + ((j >> 1) << 3);
                    skipv[n][j] = (row < Ll)
                        ? __ldg(&g_skip[(size_t)(b*Cc + cc)*Ll + row]) : 0.f;
                }
            }
        }

        // ---- prefetch next tile's A (hidden behind GEMM2 + writeout) ----
        uint32_t nDh[2][4], nDl[2][4], nTh[2][4], nTl[2][4];
        if (it + 1 < TILES_PER_CTA)
            load_A(hb, trow0 + 128, dil, tig, nDh, nDl, nTh, nTl);

        // ---- GEMM2: E[128,64] = O[128,32] x W2^T (reuse acc) ----
        #pragma unroll
        for (int n = 0; n < 8; ++n)
            #pragma unroll
            for (int j = 0; j < 4; ++j) acc[n][j] = 0.f;

        #pragma unroll
        for (int kt = 0; kt < 2; ++kt) {
            #pragma unroll
            for (int n = 0; n < 8; ++n) {
                const __nv_bfloat16* pb = sW2hi + (n*8 + r0)*STR_W2 + kt*16 + tig*2;
                const __nv_bfloat16* pq = sW2lo + (n*8 + r0)*STR_W2 + kt*16 + tig*2;
                uint32_t bh[2] = { ld32s(pb), ld32s(pb + 8) };
                uint32_t bl[2] = { ld32s(pq), ld32s(pq + 8) };
                mma_bf16(acc[n], a2h[kt], bh);
                mma_bf16(acc[n], a2h[kt], bl);
                mma_bf16(acc[n], a2l[kt], bh);
            }
        }

        // ---- writeout: skip (+)= s+bs ; h_out = h(frag) + r+br ----
        #pragma unroll
        for (int n = 0; n < 4; ++n) {
            #pragma unroll
            for (int jh = 0; jh < 2; ++jh) {     // row half
                const int row = trow0 + (jh << 3);
                if (row < Ll) {
                    // h pair for channels (n*8+tig*2, +1) at this row, from tap-t frags
                    float2 hp = bf2sum(aTh[n>>1][(n&1)*2 + jh], aTl[n>>1][(n&1)*2 + jh]);
                    #pragma unroll
                    for (int ce = 0; ce < 2; ++ce) {
                        const int j  = jh*2 + ce;
                        const int cc = n*8 + tig*2 + ce;
                        const size_t idx = (size_t)(b*Cc + cc)*Ll + row;
                        const float sv = acc[n][j] + sBias[64 + cc];
                        g_skip[idx] = FIRST ? sv : (skipv[n][j] + sv);
                        const float hv = ce ? hp.y : hp.x;
                        h_out[idx] = hv + acc[n+4][j] + sBias[96 + cc];
                    }
                }
            }
        }

        // ---- rotate prefetched A into place ----
        if (it + 1 < TILES_PER_CTA) {
            #pragma unroll
            for (int kt = 0; kt < 2; ++kt)
                #pragma unroll
                for (int ri = 0; ri < 4; ++ri) {
                    aDh[kt][ri] = nDh[kt][ri]; aDl[kt][ri] = nDl[kt][ri];
                    aTh[kt][ri] = nTh[kt][ri]; aTl[kt][ri] = nTl[kt][ri];
                }
        }
    }
}

// ---------------- downsample conv ----------------
__global__ void __launch_bounds__(256, 2)
downsample_kernel(const float* __restrict__ wd, const float* __restrict__ bd)
{
    extern __shared__ float smem[];
    float4* sWd = (float4*)smem;
    float*  sSk = smem + 8192;

    int tid = threadIdx.x;
    int b   = blockIdx.y;
    int u0  = blockIdx.x * 64;
    int t0  = u0 * 4;

    const float4* wd4 = (const float4*)wd;
    for (int e = tid; e < 2048; e += 256) sWd[e] = wd4[e];

    const float* skb = g_skip + (size_t)b * Cc * Ll;
    for (int e = tid; e < 32*256; e += 256) {
        int c = e >> 8, j = e & 255;
        int gt = t0 + j;
        sSk[c*256 + j] = (gt < Ll) ? skb[c*Ll + gt] : 0.0f;
    }
    __syncthreads();

    int op = tid >> 3;
    int o0 = op, o1 = op + 32;
    int qq = tid & 7;
    float a0[8], a1[8];
    float bd0 = bd[o0], bd1 = bd[o1];
    #pragma unroll
    for (int i = 0; i < 8; ++i) { a0[i]=bd0; a1[i]=bd1; }

    #pragma unroll 4
    for (int c = 0; c < 32; ++c) {
        float4 w0v = sWd[o0*32 + c];
        float4 w1v = sWd[o1*32 + c];
        const float* sr = sSk + c*256;
        #pragma unroll
        for (int i = 0; i < 8; ++i) {
            float4 sv = *(const float4*)(sr + (i*8 + qq)*4);
            a0[i] += w0v.x*sv.x + w0v.y*sv.y + w0v.z*sv.z + w0v.w*sv.w;
            a1[i] += w1v.x*sv.x + w1v.y*sv.y + w1v.z*sv.z + w1v.w*sv.w;
        }
    }
    float* yb = g_y + (size_t)b * FLATN;
    #pragma unroll
    for (int i = 0; i < 8; ++i) {
        int u = u0 + i*8 + qq;
        if (u < DOWNL) {
            yb[o0*DOWNL + u] = a0[i];
            yb[o1*DOWNL + u] = a1[i];
        }
    }
}

// ---------------- FC ----------------
__global__ void zero_o_kernel() {
    int i = threadIdx.x;
    if (i < Bb*64) g_o[i] = 0.0f;
}

#define FC_CHUNK 2000
__global__ void __launch_bounds__(512, 2)
fc_kernel(const float* __restrict__ fcW)
{
    extern __shared__ float smem[];
    int tid = threadIdx.x;
    int f0  = blockIdx.x * FC_CHUNK;
    int mg  = blockIdx.y;

    for (int e = tid; e < 8*FC_CHUNK/4; e += 512) {
        int b = e / (FC_CHUNK/4), f4 = e - b*(FC_CHUNK/4);
        ((float4*)smem)[b*(FC_CHUNK/4) + f4] =
            *(const float4*)(g_y + (size_t)b*FLATN + f0 + f4*4);
    }
    __syncthreads();

    int w = tid >> 5, lane = tid & 31;
    int m0 = mg*32 + w;
    float acc0[8], acc1[8];
    #pragma unroll
    for (int b = 0; b < 8; ++b) { acc0[b]=0.f; acc1[b]=0.f; }

    const float4* W0 = (const float4*)(fcW + (size_t)m0      * FLATN + f0);
    const float4* W1 = (const float4*)(fcW + (size_t)(m0+16) * FLATN + f0);
    for (int i4 = lane; i4 < FC_CHUNK/4; i4 += 32) {
        float4 wv0 = __ldg(W0 + i4);
        float4 wv1 = __ldg(W1 + i4);
        #pragma unroll
        for (int b = 0; b < 8; ++b) {
            float4 yv = ((const float4*)smem)[b*(FC_CHUNK/4) + i4];
            acc0[b] += wv0.x*yv.x + wv0.y*yv.y + wv0.z*yv.z + wv0.w*yv.w;
            acc1[b] += wv1.x*yv.x + wv1.y*yv.y + wv1.z*yv.z + wv1.w*yv.w;
        }
    }
    #pragma unroll
    for (int off = 16; off; off >>= 1) {
        #pragma unroll
        for (int b = 0; b < 8; ++b) {
            acc0[b] += __shfl_xor_sync(0xFFFFFFFFu, acc0[b], off);
            acc1[b] += __shfl_xor_sync(0xFFFFFFFFu, acc1[b], off);
        }
    }
    if (lane == 0) {
        #pragma unroll
        for (int b = 0; b < 8; ++b) {
            atomicAdd(&g_o[b*64 + m0],      acc0[b]);
            atomicAdd(&g_o[b*64 + m0 + 16], acc1[b]);
        }
    }
}

// ---------------- final ----------------
__global__ void final_kernel(const float* __restrict__ eps,
                             const float* __restrict__ fcb,
                             float* __restrict__ out)
{
    int i = threadIdx.x;
    int b = i >> 5, l = i & 31;
    float mu = g_o[b*64 + l]      + fcb[l];
    float lv = g_o[b*64 + 32 + l] + fcb[32 + l];
    float z  = mu + eps[b*32 + l] * expf(0.5f * lv);
    out[i]       = mu;
    out[256 + i] = lv;
    out[512 + i] = z;
}

// ---------------- launch ----------------
extern "C" void kernel_launch(void* const* d_in, const int* in_sizes, int n_in,
                              void* d_out, int out_size)
{
    (void)in_sizes; (void)n_in; (void)out_size;
    const float* x   = (const float*)d_in[0];
    const float* eps = (const float*)d_in[1];
    const float* w0  = (const float*)d_in[2];
    const float* b0  = (const float*)d_in[3];
    const float* Wf  = (const float*)d_in[4];
    const float* bf  = (const float*)d_in[5];
    const float* Wg  = (const float*)d_in[6];
    const float* bg  = (const float*)d_in[7];
    const float* Ws  = (const float*)d_in[8];
    const float* bs  = (const float*)d_in[9];
    const float* Wr  = (const float*)d_in[10];
    const float* br  = (const float*)d_in[11];
    const float* wd  = (const float*)d_in[12];
    const float* bd  = (const float*)d_in[13];
    const float* fcW = (const float*)d_in[14];
    const float* fcb = (const float*)d_in[15];
    float* out = (float*)d_out;

    cudaFuncSetAttribute(wn_block_mma<true>,  cudaFuncAttributeMaxDynamicSharedMemorySize, SMEM_BLK);
    cudaFuncSetAttribute(wn_block_mma<false>, cudaFuncAttributeMaxDynamicSharedMemorySize, SMEM_BLK);
    cudaFuncSetAttribute(downsample_kernel,   cudaFuncAttributeMaxDynamicSharedMemorySize, 65536);
    cudaFuncSetAttribute(fc_kernel,           cudaFuncAttributeMaxDynamicSharedMemorySize, 8*FC_CHUNK*4);

    conv0_kernel<<<dim3((Ll + 255)/256, Bb*Cc), 256>>>(x, w0, b0);

    dim3 bgrid(704 / TILES_PER_CTA, Bb);
    for (int i = 0; i < 6; ++i) {
        int dil = 1 << i;
        int ping = i & 1;
        const float* wfp = Wf + i*2048; const float* wgp = Wg + i*2048;
        const float* wsp = Ws + i*1024; const float* wrp = Wr + i*1024;
        const float* bfi = bf + i*32;   const float* bgi = bg + i*32;
        const float* bsi = bs + i*32;   const float* bri = br + i*32;
        if (i == 0)
            wn_block_mma<true ><<<bgrid, 256, SMEM_BLK>>>(ping, dil, wfp, wgp, wsp, wrp, bfi, bgi, bsi, bri);
        else
            wn_block_mma<false><<<bgrid, 256, SMEM_BLK>>>(ping, dil, wfp, wgp, wsp, wrp, bfi, bgi, bsi, bri);
    }

    downsample_kernel<<<dim3((DOWNL + 63)/64, Bb), 256, 65536>>>(wd, bd);
    zero_o_kernel<<<1, 512>>>();
    fc_kernel<<<dim3(FLATN/FC_CHUNK, 2), 512, 8*FC_CHUNK*4>>>(fcW);
    final_kernel<<<1, 256>>>(eps, fcb, out);
}

// round 8
// speedup vs baseline: 2.6500x; 1.1472x over previous
#include <cuda_runtime.h>
#include <cuda_bf16.h>
#include <cstdint>
#include <math.h>

#define Bb   8
#define Cc   32
#define Ll   90000
#define DOWNL 22500
#define FLATN 1440000

#define TOUT  192
#define TPBT  469           // ceil(90000/192)
#define NT    (Bb*TPBT)     // 3752
#define GRIDP 148
#define NTHR  512

// ---- scratch ----
__device__ float g_skip[Bb*Cc*Ll];
__device__ float g_y[Bb*FLATN];
__device__ float g_o[Bb*64];

__device__ __forceinline__ float fsig(float x)  { return 1.0f / (1.0f + __expf(-x)); }
__device__ __forceinline__ float ftanh(float x) { return 2.0f * fsig(2.0f * x) - 1.0f; }

__device__ __forceinline__ void mma_bf16(float d[4], const uint32_t a[4], const uint32_t b[2]) {
    asm volatile(
        "mma.sync.aligned.m16n8k16.row.col.f32.bf16.bf16.f32 "
        "{%0,%1,%2,%3}, {%4,%5,%6,%7}, {%8,%9}, {%0,%1,%2,%3};"
        : "+f"(d[0]), "+f"(d[1]), "+f"(d[2]), "+f"(d[3])
        : "r"(a[0]), "r"(a[1]), "r"(a[2]), "r"(a[3]), "r"(b[0]), "r"(b[1]));
}
__device__ __forceinline__ uint32_t pack_hi(float a, float b, uint32_t& lo) {
    __nv_bfloat16 ha = __float2bfloat16_rn(a);
    __nv_bfloat16 hb = __float2bfloat16_rn(b);
    __nv_bfloat16 la = __float2bfloat16_rn(a - __bfloat162float(ha));
    __nv_bfloat16 lb = __float2bfloat16_rn(b - __bfloat162float(hb));
    __nv_bfloat162 h2(ha, hb), l2(la, lb);
    lo = *(uint32_t*)&l2;
    return *(uint32_t*)&h2;
}
__device__ __forceinline__ float2 bf2sum(uint32_t h, uint32_t l) {
    __nv_bfloat162 hh = *(__nv_bfloat162*)&h;
    __nv_bfloat162 ll = *(__nv_bfloat162*)&l;
    return make_float2(__bfloat162float(hh.x) + __bfloat162float(ll.x),
                       __bfloat162float(hh.y) + __bfloat162float(ll.y));
}

// ---- SMEM layout (bytes) ----
#define OFF_X     0         // 272 floats
#define OFF_CONV  1088      // w0 [32*3] + b0 [32]
#define OFF_BIAS  1600      // 6 * 128 floats (bf,bg,bs,br)
#define OFF_W1    4672      // 6 * uint2[64][36]  (hi2, lo2 interleaved)
#define OFF_W2    115264    // 6 * uint2[64][20]
#define OFF_H     176704    // uint2[256][20]
#define SMEM_TOT  217664

#define W1STR 36
#define W2STR 20
#define HSTR  20

// =========================================================================
// Fused: conv0 + 6 WaveNet blocks + skip accumulation, one persistent kernel
// =========================================================================
__global__ void __launch_bounds__(NTHR, 1)
wn_fused(const float* __restrict__ x,
         const float* __restrict__ w0g, const float* __restrict__ b0g,
         const float* __restrict__ Wf,  const float* __restrict__ bf,
         const float* __restrict__ Wg,  const float* __restrict__ bg,
         const float* __restrict__ Ws,  const float* __restrict__ bs,
         const float* __restrict__ Wr,  const float* __restrict__ br)
{
    extern __shared__ char sm[];
    float* sX    = (float*)(sm + OFF_X);
    float* sConv = (float*)(sm + OFF_CONV);
    float* sBias = (float*)(sm + OFF_BIAS);
    uint2* sW1   = (uint2*)(sm + OFF_W1);
    uint2* sW2   = (uint2*)(sm + OFF_W2);
    uint2* sH    = (uint2*)(sm + OFF_H);

    const int tid = threadIdx.x;

    // ---- one-time fills ----
    for (int e = tid; e < 96; e += NTHR) sConv[e] = w0g[e];
    for (int e = tid; e < 32; e += NTHR) sConv[96 + e] = b0g[e];
    for (int e = tid; e < 6*128; e += NTHR) {
        int i = e >> 7, r = e & 127;
        float v = (r < 32)  ? bf[i*32 + r]
                : (r < 64)  ? bg[i*32 + r - 32]
                : (r < 96)  ? bs[i*32 + r - 64]
                :             br[i*32 + r - 96];
        sBias[e] = v;
    }
    for (int e = tid; e < 6*64*32; e += NTHR) {
        int i = e >> 11, rem = e & 2047;
        int n = rem >> 5, kp = rem & 31;
        const float* wfp = Wf + i*2048;
        const float* wgp = Wg + i*2048;
        float v[2];
        #pragma unroll
        for (int q = 0; q < 2; ++q) {
            int k = kp*2 + q;
            v[q] = (n < 32)
                ? ((k < 32) ? wfp[n*64 + k*2] : wfp[n*64 + (k-32)*2 + 1])
                : ((k < 32) ? wgp[(n-32)*64 + k*2] : wgp[(n-32)*64 + (k-32)*2 + 1]);
        }
        uint32_t lo, hi = pack_hi(v[0], v[1], lo);
        sW1[i*64*W1STR + n*W1STR + kp] = make_uint2(hi, lo);
    }
    for (int e = tid; e < 6*64*16; e += NTHR) {
        int i = e >> 10, rem = e & 1023;
        int n = rem >> 4, kp = rem & 15;
        const float* wsp = Ws + i*1024;
        const float* wrp = Wr + i*1024;
        float v0 = (n < 32) ? wsp[n*32 + kp*2]     : wrp[(n-32)*32 + kp*2];
        float v1 = (n < 32) ? wsp[n*32 + kp*2 + 1] : wrp[(n-32)*32 + kp*2 + 1];
        uint32_t lo, hi = pack_hi(v0, v1, lo);
        sW2[i*64*W2STR + n*W2STR + kp] = make_uint2(hi, lo);
    }
    __syncthreads();

    const int w    = tid >> 5;
    const int lane = tid & 31;
    const int r0   = lane >> 2;
    const int tig  = lane & 3;
    const int rbase = w*16 + r0;        // this thread's rows: rbase, rbase+8

    for (int tile = blockIdx.x; tile < NT; tile += GRIDP) {
        const int b  = tile / TPBT;
        const int u  = tile - b*TPBT;
        const int g0 = u*TOUT - 64;     // local row 64 == global out start
        const float* xb = x + (size_t)b * Ll;

        // ---- x slice ----
        if (tid < 258) {
            int gx = g0 - 2 + tid;
            sX[tid] = (gx >= 0 && gx < Ll) ? xb[gx] : 0.f;
        }
        __syncthreads();

        // ---- conv0: h0 -> aT regs + sH ----
        uint32_t aTh[2][4], aTl[2][4];
        #pragma unroll
        for (int p = 0; p < 4; ++p) {
            #pragma unroll
            for (int half = 0; half < 2; ++half) {
                const int rl = rbase + half*8;
                const int grow = g0 + rl;
                float x0 = sX[rl+2], xm1 = sX[rl+1], xm2 = sX[rl];
                const int c0 = p*8 + tig*2;
                float v0 = sConv[c0*3+2]*x0 + sConv[c0*3+1]*xm1 + sConv[c0*3+0]*xm2 + sConv[96+c0];
                float v1 = sConv[(c0+1)*3+2]*x0 + sConv[(c0+1)*3+1]*xm1 + sConv[(c0+1)*3+0]*xm2 + sConv[96+c0+1];
                if (grow < 0 || grow >= Ll) { v0 = 0.f; v1 = 0.f; }
                uint32_t lo, hi = pack_hi(v0, v1, lo);
                aTh[p>>1][(p&1)*2+half] = hi;
                aTl[p>>1][(p&1)*2+half] = lo;
                sH[rl*HSTR + p*4 + tig] = make_uint2(hi, lo);
            }
        }
        __syncthreads();

        float skipacc[4][4];
        #pragma unroll
        for (int n = 0; n < 4; ++n)
            #pragma unroll
            for (int j = 0; j < 4; ++j) skipacc[n][j] = 0.f;

        #pragma unroll 1
        for (int i = 0; i < 6; ++i) {
            const int d = 1 << i;
            const uint2* W1b = sW1 + i*(64*W1STR);
            const uint2* W2b = sW2 + i*(64*W2STR);
            const float* bsm = sBias + i*128;

            // ---- dilated-tap fragments from SMEM h ----
            uint32_t aDh[2][4], aDl[2][4];
            #pragma unroll
            for (int p = 0; p < 4; ++p) {
                #pragma unroll
                for (int half = 0; half < 2; ++half) {
                    int rl = rbase + half*8 - d;
                    if (rl < 0) rl = 0;              // garbage only in invalid halo
                    uint2 v = sH[rl*HSTR + p*4 + tig];
                    aDh[p>>1][(p&1)*2+half] = v.x;
                    aDl[p>>1][(p&1)*2+half] = v.y;
                }
            }
            __syncthreads();   // all reads done before any h writes below

            // ---- GEMM1: D = A x W1^T (3-term hi/lo) ----
            float acc[8][4];
            #pragma unroll
            for (int n = 0; n < 8; ++n)
                #pragma unroll
                for (int j = 0; j < 4; ++j) acc[n][j] = 0.f;

            #pragma unroll
            for (int kt = 0; kt < 2; ++kt) {
                #pragma unroll
                for (int n = 0; n < 8; ++n) {
                    uint2 wa = W1b[(n*8+r0)*W1STR + kt*8 + tig];
                    uint2 wb = W1b[(n*8+r0)*W1STR + kt*8 + tig + 4];
                    uint32_t bh[2] = { wa.x, wb.x };
                    uint32_t bl[2] = { wa.y, wb.y };
                    mma_bf16(acc[n], aDh[kt], bh);
                    mma_bf16(acc[n], aDh[kt], bl);
                    mma_bf16(acc[n], aDl[kt], bh);
                }
            }
            #pragma unroll
            for (int kt = 0; kt < 2; ++kt) {
                #pragma unroll
                for (int n = 0; n < 8; ++n) {
                    uint2 wa = W1b[(n*8+r0)*W1STR + (2+kt)*8 + tig];
                    uint2 wb = W1b[(n*8+r0)*W1STR + (2+kt)*8 + tig + 4];
                    uint32_t bh[2] = { wa.x, wb.x };
                    uint32_t bl[2] = { wa.y, wb.y };
                    mma_bf16(acc[n], aTh[kt], bh);
                    mma_bf16(acc[n], aTh[kt], bl);
                    mma_bf16(acc[n], aTl[kt], bh);
                }
            }

            // ---- epilogue 1: gated activation -> GEMM2 A-frags ----
            uint32_t a2h[2][4], a2l[2][4];
            #pragma unroll
            for (int nn = 0; nn < 4; ++nn) {
                const int c = nn*8 + tig*2;
                const float b0f = bsm[c],    b1f = bsm[c+1];
                const float b0g = bsm[32+c], b1g = bsm[32+c+1];
                float o0 = ftanh(acc[nn][0] + b0f) * fsig(acc[nn+4][0] + b0g);
                float o1 = ftanh(acc[nn][1] + b1f) * fsig(acc[nn+4][1] + b1g);
                float o2 = ftanh(acc[nn][2] + b0f) * fsig(acc[nn+4][2] + b0g);
                float o3 = ftanh(acc[nn][3] + b1f) * fsig(acc[nn+4][3] + b1g);
                const int kt2 = nn >> 1;
                const int ri  = (nn & 1)*2;
                a2h[kt2][ri]     = pack_hi(o0, o1, a2l[kt2][ri]);
                a2h[kt2][ri + 1] = pack_hi(o2, o3, a2l[kt2][ri + 1]);
            }

            // ---- GEMM2: [s | r] = O x W2^T ----
            #pragma unroll
            for (int n = 0; n < 8; ++n)
                #pragma unroll
                for (int j = 0; j < 4; ++j) acc[n][j] = 0.f;

            #pragma unroll
            for (int kt = 0; kt < 2; ++kt) {
                #pragma unroll
                for (int n = 0; n < 8; ++n) {
                    uint2 wa = W2b[(n*8+r0)*W2STR + kt*8 + tig];
                    uint2 wb = W2b[(n*8+r0)*W2STR + kt*8 + tig + 4];
                    uint32_t bh[2] = { wa.x, wb.x };
                    uint32_t bl[2] = { wa.y, wb.y };
                    mma_bf16(acc[n], a2h[kt], bh);
                    mma_bf16(acc[n], a2h[kt], bl);
                    mma_bf16(acc[n], a2l[kt], bh);
                }
            }

            // ---- skip += s + bs ; h = h + r + br (regs + SMEM) ----
            #pragma unroll
            for (int p = 0; p < 4; ++p) {
                #pragma unroll
                for (int half = 0; half < 2; ++half) {
                    const int rl = rbase + half*8;
                    const int grow = g0 + rl;
                    const int c0 = p*8 + tig*2;
                    const int j0 = half*2;
                    float2 hp = bf2sum(aTh[p>>1][(p&1)*2+half], aTl[p>>1][(p&1)*2+half]);
                    skipacc[p][j0]   += acc[p][j0]   + bsm[64+c0];
                    skipacc[p][j0+1] += acc[p][j0+1] + bsm[64+c0+1];
                    float hv0 = hp.x + acc[p+4][j0]   + bsm[96+c0];
                    float hv1 = hp.y + acc[p+4][j0+1] + bsm[96+c0+1];
                    if (grow < 0) { hv0 = 0.f; hv1 = 0.f; }   // causal zero-pad semantics
                    uint32_t lo, hi = pack_hi(hv0, hv1, lo);
                    aTh[p>>1][(p&1)*2+half] = hi;
                    aTl[p>>1][(p&1)*2+half] = lo;
                    sH[rl*HSTR + p*4 + tig] = make_uint2(hi, lo);
                }
            }
            __syncthreads();   // h_{i+1} visible for next block's dilated taps
        }

        // ---- writeout: single skip store per element ----
        #pragma unroll
        for (int p = 0; p < 4; ++p) {
            #pragma unroll
            for (int half = 0; half < 2; ++half) {
                const int rl = rbase + half*8;
                if (rl >= 64) {
                    const int grow = g0 + rl;
                    if (grow < Ll) {
                        const int c0 = p*8 + tig*2;
                        const size_t i0 = (size_t)(b*Cc + c0)*Ll + grow;
                        g_skip[i0]      = skipacc[p][half*2];
                        g_skip[i0 + Ll] = skipacc[p][half*2 + 1];
                    }
                }
            }
        }
    }
}

// ---------------- downsample conv ----------------
__global__ void __launch_bounds__(256, 2)
downsample_kernel(const float* __restrict__ wd, const float* __restrict__ bd)
{
    extern __shared__ float smem[];
    float4* sWd = (float4*)smem;
    float*  sSk = smem + 8192;

    int tid = threadIdx.x;
    int b   = blockIdx.y;
    int u0  = blockIdx.x * 64;
    int t0  = u0 * 4;

    const float4* wd4 = (const float4*)wd;
    for (int e = tid; e < 2048; e += 256) sWd[e] = wd4[e];

    const float* skb = g_skip + (size_t)b * Cc * Ll;
    for (int e = tid; e < 32*256; e += 256) {
        int c = e >> 8, j = e & 255;
        int gt = t0 + j;
        sSk[c*256 + j] = (gt < Ll) ? skb[c*Ll + gt] : 0.0f;
    }
    __syncthreads();

    int op = tid >> 3;
    int o0 = op, o1 = op + 32;
    int qq = tid & 7;
    float a0[8], a1[8];
    float bd0 = bd[o0], bd1 = bd[o1];
    #pragma unroll
    for (int i = 0; i < 8; ++i) { a0[i]=bd0; a1[i]=bd1; }

    #pragma unroll 4
    for (int c = 0; c < 32; ++c) {
        float4 w0v = sWd[o0*32 + c];
        float4 w1v = sWd[o1*32 + c];
        const float* sr = sSk + c*256;
        #pragma unroll
        for (int i = 0; i < 8; ++i) {
            float4 sv = *(const float4*)(sr + (i*8 + qq)*4);
            a0[i] += w0v.x*sv.x + w0v.y*sv.y + w0v.z*sv.z + w0v.w*sv.w;
            a1[i] += w1v.x*sv.x + w1v.y*sv.y + w1v.z*sv.z + w1v.w*sv.w;
        }
    }
    float* yb = g_y + (size_t)b * FLATN;
    #pragma unroll
    for (int i = 0; i < 8; ++i) {
        int u = u0 + i*8 + qq;
        if (u < DOWNL) {
            yb[o0*DOWNL + u] = a0[i];
            yb[o1*DOWNL + u] = a1[i];
        }
    }
}

// ---------------- FC ----------------
__global__ void zero_o_kernel() {
    int i = threadIdx.x;
    if (i < Bb*64) g_o[i] = 0.0f;
}

#define FC_CHUNK 2000
__global__ void __launch_bounds__(512, 2)
fc_kernel(const float* __restrict__ fcW)
{
    extern __shared__ float smem[];
    int tid = threadIdx.x;
    int f0  = blockIdx.x * FC_CHUNK;
    int mg  = blockIdx.y;

    for (int e = tid; e < 8*FC_CHUNK/4; e += 512) {
        int b = e / (FC_CHUNK/4), f4 = e - b*(FC_CHUNK/4);
        ((float4*)smem)[b*(FC_CHUNK/4) + f4] =
            *(const float4*)(g_y + (size_t)b*FLATN + f0 + f4*4);
    }
    __syncthreads();

    int w = tid >> 5, lane = tid & 31;
    int m0 = mg*32 + w;
    float acc0[8], acc1[8];
    #pragma unroll
    for (int b = 0; b < 8; ++b) { acc0[b]=0.f; acc1[b]=0.f; }

    const float4* W0 = (const float4*)(fcW + (size_t)m0      * FLATN + f0);
    const float4* W1 = (const float4*)(fcW + (size_t)(m0+16) * FLATN + f0);
    for (int i4 = lane; i4 < FC_CHUNK/4; i4 += 32) {
        float4 wv0 = __ldg(W0 + i4);
        float4 wv1 = __ldg(W1 + i4);
        #pragma unroll
        for (int b = 0; b < 8; ++b) {
            float4 yv = ((const float4*)smem)[b*(FC_CHUNK/4) + i4];
            acc0[b] += wv0.x*yv.x + wv0.y*yv.y + wv0.z*yv.z + wv0.w*yv.w;
            acc1[b] += wv1.x*yv.x + wv1.y*yv.y + wv1.z*yv.z + wv1.w*yv.w;
        }
    }
    #pragma unroll
    for (int off = 16; off; off >>= 1) {
        #pragma unroll
        for (int b = 0; b < 8; ++b) {
            acc0[b] += __shfl_xor_sync(0xFFFFFFFFu, acc0[b], off);
            acc1[b] += __shfl_xor_sync(0xFFFFFFFFu, acc1[b], off);
        }
    }
    if (lane == 0) {
        #pragma unroll
        for (int b = 0; b < 8; ++b) {
            atomicAdd(&g_o[b*64 + m0],      acc0[b]);
            atomicAdd(&g_o[b*64 + m0 + 16], acc1[b]);
        }
    }
}

// ---------------- final ----------------
__global__ void final_kernel(const float* __restrict__ eps,
                             const float* __restrict__ fcb,
                             float* __restrict__ out)
{
    int i = threadIdx.x;
    int b = i >> 5, l = i & 31;
    float mu = g_o[b*64 + l]      + fcb[l];
    float lv = g_o[b*64 + 32 + l] + fcb[32 + l];
    float z  = mu + eps[b*32 + l] * expf(0.5f * lv);
    out[i]       = mu;
    out[256 + i] = lv;
    out[512 + i] = z;
}

// ---------------- launch ----------------
extern "C" void kernel_launch(void* const* d_in, const int* in_sizes, int n_in,
                              void* d_out, int out_size)
{
    (void)in_sizes; (void)n_in; (void)out_size;
    const float* x   = (const float*)d_in[0];
    const float* eps = (const float*)d_in[1];
    const float* w0  = (const float*)d_in[2];
    const float* b0  = (const float*)d_in[3];
    const float* Wf  = (const float*)d_in[4];
    const float* bf  = (const float*)d_in[5];
    const float* Wg  = (const float*)d_in[6];
    const float* bg  = (const float*)d_in[7];
    const float* Ws  = (const float*)d_in[8];
    const float* bs  = (const float*)d_in[9];
    const float* Wr  = (const float*)d_in[10];
    const float* br  = (const float*)d_in[11];
    const float* wd  = (const float*)d_in[12];
    const float* bd  = (const float*)d_in[13];
    const float* fcW = (const float*)d_in[14];
    const float* fcb = (const float*)d_in[15];
    float* out = (float*)d_out;

    cudaFuncSetAttribute(wn_fused, cudaFuncAttributeMaxDynamicSharedMemorySize, SMEM_TOT);
    cudaFuncSetAttribute(downsample_kernel, cudaFuncAttributeMaxDynamicSharedMemorySize, 65536);
    cudaFuncSetAttribute(fc_kernel, cudaFuncAttributeMaxDynamicSharedMemorySize, 8*FC_CHUNK*4);

    wn_fused<<<GRIDP, NTHR, SMEM_TOT>>>(x, w0, b0, Wf, bf, Wg, bg, Ws, bs, Wr, br);
    downsample_kernel<<<dim3((DOWNL + 63)/64, Bb), 256, 65536>>>(wd, bd);
    zero_o_kernel<<<1, 512>>>();
    fc_kernel<<<dim3(FLATN/FC_CHUNK, 2), 512, 8*FC_CHUNK*4>>>(fcW);
    final_kernel<<<1, 256>>>(eps, fcb, out);
}

// round 9
// speedup vs baseline: 3.0817x; 1.1629x over previous
#include <cuda_runtime.h>
#include <cuda_bf16.h>
#include <cstdint>
#include <math.h>

#define Bb   8
#define Cc   32
#define Ll   90000
#define DOWNL 22500
#define FLATN 1440000

#define TOUT  192
#define TPBT  469
#define NT    (Bb*TPBT)
#define GRIDP 148
#define NTHR  256

// ---- scratch ----
__device__ float g_skip[Bb*Cc*Ll];
__device__ float g_y[Bb*FLATN];
__device__ float g_o[Bb*64];

__device__ __forceinline__ void mma_bf16(float d[4], const uint32_t a[4], const uint32_t b[2]) {
    asm volatile(
        "mma.sync.aligned.m16n8k16.row.col.f32.bf16.bf16.f32 "
        "{%0,%1,%2,%3}, {%4,%5,%6,%7}, {%8,%9}, {%0,%1,%2,%3};"
        : "+f"(d[0]), "+f"(d[1]), "+f"(d[2]), "+f"(d[3])
        : "r"(a[0]), "r"(a[1]), "r"(a[2]), "r"(a[3]), "r"(b[0]), "r"(b[1]));
}
__device__ __forceinline__ uint32_t pack_hi(float a, float b, uint32_t& lo) {
    __nv_bfloat16 ha = __float2bfloat16_rn(a);
    __nv_bfloat16 hb = __float2bfloat16_rn(b);
    __nv_bfloat16 la = __float2bfloat16_rn(a - __bfloat162float(ha));
    __nv_bfloat16 lb = __float2bfloat16_rn(b - __bfloat162float(hb));
    __nv_bfloat162 h2(ha, hb), l2(la, lb);
    lo = *(uint32_t*)&l2;
    return *(uint32_t*)&h2;
}
__device__ __forceinline__ float2 bf2sum(uint32_t h, uint32_t l) {
    __nv_bfloat162 hh = *(__nv_bfloat162*)&h;
    __nv_bfloat162 ll = *(__nv_bfloat162*)&l;
    return make_float2(__bfloat162float(hh.x) + __bfloat162float(ll.x),
                       __bfloat162float(hh.y) + __bfloat162float(ll.y));
}
// o = tanh(f)*sigmoid(g) = (1-u)/((1+u)(1+v)), u=e^{-2f}, v=e^{-g}
__device__ __forceinline__ float gated(float f, float g) {
    f = fminf(fmaxf(f, -15.f), 15.f);
    g = fminf(fmaxf(g, -30.f), 30.f);
    float u = __expf(-2.f * f);
    float v = __expf(-g);
    return __fdividef(1.f - u, (1.f + u) * (1.f + v));
}

// ---- SMEM layout (bytes) ----
#define OFF_X     0
#define OFF_CONV  1088
#define OFF_BIAS  1600
#define OFF_W1    4672
#define OFF_W2    115264
#define OFF_H     176704
#define SMEM_TOT  217664

#define W1STR 36
#define W2STR 20
#define HSTR  20

// =========================================================================
// Fused conv0 + 6 blocks; 8 warps, each warp owns TWO m16 row-tiles (m32)
// =========================================================================
__global__ void __launch_bounds__(NTHR, 1)
wn_fused(const float* __restrict__ x,
         const float* __restrict__ w0g, const float* __restrict__ b0g,
         const float* __restrict__ Wf,  const float* __restrict__ bf,
         const float* __restrict__ Wg,  const float* __restrict__ bg,
         const float* __restrict__ Ws,  const float* __restrict__ bs,
         const float* __restrict__ Wr,  const float* __restrict__ br)
{
    extern __shared__ char sm[];
    float* sX    = (float*)(sm + OFF_X);
    float* sConv = (float*)(sm + OFF_CONV);
    float* sBias = (float*)(sm + OFF_BIAS);
    uint2* sW1   = (uint2*)(sm + OFF_W1);
    uint2* sW2   = (uint2*)(sm + OFF_W2);
    uint2* sH    = (uint2*)(sm + OFF_H);

    const int tid = threadIdx.x;

    for (int e = tid; e < 96; e += NTHR) sConv[e] = w0g[e];
    for (int e = tid; e < 32; e += NTHR) sConv[96 + e] = b0g[e];
    for (int e = tid; e < 6*128; e += NTHR) {
        int i = e >> 7, r = e & 127;
        float v = (r < 32)  ? bf[i*32 + r]
                : (r < 64)  ? bg[i*32 + r - 32]
                : (r < 96)  ? bs[i*32 + r - 64]
                :             br[i*32 + r - 96];
        sBias[e] = v;
    }
    for (int e = tid; e < 6*64*32; e += NTHR) {
        int i = e >> 11, rem = e & 2047;
        int n = rem >> 5, kp = rem & 31;
        const float* wfp = Wf + i*2048;
        const float* wgp = Wg + i*2048;
        float v[2];
        #pragma unroll
        for (int q = 0; q < 2; ++q) {
            int k = kp*2 + q;
            v[q] = (n < 32)
                ? ((k < 32) ? wfp[n*64 + k*2] : wfp[n*64 + (k-32)*2 + 1])
                : ((k < 32) ? wgp[(n-32)*64 + k*2] : wgp[(n-32)*64 + (k-32)*2 + 1]);
        }
        uint32_t lo, hi = pack_hi(v[0], v[1], lo);
        sW1[i*64*W1STR + n*W1STR + kp] = make_uint2(hi, lo);
    }
    for (int e = tid; e < 6*64*16; e += NTHR) {
        int i = e >> 10, rem = e & 1023;
        int n = rem >> 4, kp = rem & 15;
        const float* wsp = Ws + i*1024;
        const float* wrp = Wr + i*1024;
        float v0 = (n < 32) ? wsp[n*32 + kp*2]     : wrp[(n-32)*32 + kp*2];
        float v1 = (n < 32) ? wsp[n*32 + kp*2 + 1] : wrp[(n-32)*32 + kp*2 + 1];
        uint32_t lo, hi = pack_hi(v0, v1, lo);
        sW2[i*64*W2STR + n*W2STR + kp] = make_uint2(hi, lo);
    }
    __syncthreads();

    const int w    = tid >> 5;
    const int lane = tid & 31;
    const int r0   = lane >> 2;
    const int tig  = lane & 3;
    const int rb0  = w*32 + r0;          // mt=0 rows: rb0, rb0+8 ; mt=1: +16

    for (int tile = blockIdx.x; tile < NT; tile += GRIDP) {
        const int b  = tile / TPBT;
        const int u  = tile - b*TPBT;
        const int g0 = u*TOUT - 64;
        const float* xb = x + (size_t)b * Ll;

        for (int e = tid; e < 258; e += NTHR) {
            int gx = g0 - 2 + e;
            sX[e] = (gx >= 0 && gx < Ll) ? xb[gx] : 0.f;
        }
        __syncthreads();

        // ---- conv0 -> aT regs + sH ----
        uint32_t aTh[2][2][4], aTl[2][2][4];
        #pragma unroll
        for (int mt = 0; mt < 2; ++mt) {
            #pragma unroll
            for (int p = 0; p < 4; ++p) {
                #pragma unroll
                for (int half = 0; half < 2; ++half) {
                    const int rl = rb0 + mt*16 + half*8;
                    const int grow = g0 + rl;
                    float x0 = sX[rl+2], xm1 = sX[rl+1], xm2 = sX[rl];
                    const int c0 = p*8 + tig*2;
                    float v0 = sConv[c0*3+2]*x0 + sConv[c0*3+1]*xm1 + sConv[c0*3+0]*xm2 + sConv[96+c0];
                    float v1 = sConv[(c0+1)*3+2]*x0 + sConv[(c0+1)*3+1]*xm1 + sConv[(c0+1)*3+0]*xm2 + sConv[96+c0+1];
                    if (grow < 0 || grow >= Ll) { v0 = 0.f; v1 = 0.f; }
                    uint32_t lo, hi = pack_hi(v0, v1, lo);
                    aTh[mt][p>>1][(p&1)*2+half] = hi;
                    aTl[mt][p>>1][(p&1)*2+half] = lo;
                    sH[rl*HSTR + p*4 + tig] = make_uint2(hi, lo);
                }
            }
        }
        __syncthreads();

        float skipacc[2][4][4];
        #pragma unroll
        for (int mt = 0; mt < 2; ++mt)
            #pragma unroll
            for (int n = 0; n < 4; ++n)
                #pragma unroll
                for (int j = 0; j < 4; ++j) skipacc[mt][n][j] = 0.f;

        #pragma unroll 1
        for (int i = 0; i < 6; ++i) {
            const int d = 1 << i;
            const uint2* W1b = sW1 + i*(64*W1STR);
            const uint2* W2b = sW2 + i*(64*W2STR);
            const float* bsm = sBias + i*128;

            uint32_t aDh[2][2][4], aDl[2][2][4];
            #pragma unroll
            for (int mt = 0; mt < 2; ++mt) {
                #pragma unroll
                for (int p = 0; p < 4; ++p) {
                    #pragma unroll
                    for (int half = 0; half < 2; ++half) {
                        int rl = rb0 + mt*16 + half*8 - d;
                        if (rl < 0) rl = 0;
                        uint2 v = sH[rl*HSTR + p*4 + tig];
                        aDh[mt][p>>1][(p&1)*2+half] = v.x;
                        aDl[mt][p>>1][(p&1)*2+half] = v.y;
                    }
                }
            }
            __syncthreads();

            // ---- GEMM1 (B-frags loaded once, reused for both m-tiles) ----
            float acc[2][8][4];
            #pragma unroll
            for (int mt = 0; mt < 2; ++mt)
                #pragma unroll
                for (int n = 0; n < 8; ++n)
                    #pragma unroll
                    for (int j = 0; j < 4; ++j) acc[mt][n][j] = 0.f;

            #pragma unroll
            for (int kt = 0; kt < 2; ++kt) {
                #pragma unroll
                for (int n = 0; n < 8; ++n) {
                    uint2 wa = W1b[(n*8+r0)*W1STR + kt*8 + tig];
                    uint2 wb = W1b[(n*8+r0)*W1STR + kt*8 + tig + 4];
                    uint32_t bh[2] = { wa.x, wb.x };
                    uint32_t bl[2] = { wa.y, wb.y };
                    #pragma unroll
                    for (int mt = 0; mt < 2; ++mt) {
                        mma_bf16(acc[mt][n], aDh[mt][kt], bh);
                        mma_bf16(acc[mt][n], aDh[mt][kt], bl);
                        mma_bf16(acc[mt][n], aDl[mt][kt], bh);
                    }
                }
            }
            #pragma unroll
            for (int kt = 0; kt < 2; ++kt) {
                #pragma unroll
                for (int n = 0; n < 8; ++n) {
                    uint2 wa = W1b[(n*8+r0)*W1STR + (2+kt)*8 + tig];
                    uint2 wb = W1b[(n*8+r0)*W1STR + (2+kt)*8 + tig + 4];
                    uint32_t bh[2] = { wa.x, wb.x };
                    uint32_t bl[2] = { wa.y, wb.y };
                    #pragma unroll
                    for (int mt = 0; mt < 2; ++mt) {
                        mma_bf16(acc[mt][n], aTh[mt][kt], bh);
                        mma_bf16(acc[mt][n], aTh[mt][kt], bl);
                        mma_bf16(acc[mt][n], aTl[mt][kt], bh);
                    }
                }
            }

            // ---- epilogue 1: gated activation -> GEMM2 A-frags ----
            uint32_t a2h[2][2][4], a2l[2][2][4];
            #pragma unroll
            for (int mt = 0; mt < 2; ++mt) {
                #pragma unroll
                for (int nn = 0; nn < 4; ++nn) {
                    const int c = nn*8 + tig*2;
                    const float b0f = bsm[c],    b1f = bsm[c+1];
                    const float b0g = bsm[32+c], b1g = bsm[32+c+1];
                    float o0 = gated(acc[mt][nn][0] + b0f, acc[mt][nn+4][0] + b0g);
                    float o1 = gated(acc[mt][nn][1] + b1f, acc[mt][nn+4][1] + b1g);
                    float o2 = gated(acc[mt][nn][2] + b0f, acc[mt][nn+4][2] + b0g);
                    float o3 = gated(acc[mt][nn][3] + b1f, acc[mt][nn+4][3] + b1g);
                    const int kt2 = nn >> 1;
                    const int ri  = (nn & 1)*2;
                    a2h[mt][kt2][ri]     = pack_hi(o0, o1, a2l[mt][kt2][ri]);
                    a2h[mt][kt2][ri + 1] = pack_hi(o2, o3, a2l[mt][kt2][ri + 1]);
                }
            }

            // ---- GEMM2 ----
            #pragma unroll
            for (int mt = 0; mt < 2; ++mt)
                #pragma unroll
                for (int n = 0; n < 8; ++n)
                    #pragma unroll
                    for (int j = 0; j < 4; ++j) acc[mt][n][j] = 0.f;

            #pragma unroll
            for (int kt = 0; kt < 2; ++kt) {
                #pragma unroll
                for (int n = 0; n < 8; ++n) {
                    uint2 wa = W2b[(n*8+r0)*W2STR + kt*8 + tig];
                    uint2 wb = W2b[(n*8+r0)*W2STR + kt*8 + tig + 4];
                    uint32_t bh[2] = { wa.x, wb.x };
                    uint32_t bl[2] = { wa.y, wb.y };
                    #pragma unroll
                    for (int mt = 0; mt < 2; ++mt) {
                        mma_bf16(acc[mt][n], a2h[mt][kt], bh);
                        mma_bf16(acc[mt][n], a2h[mt][kt], bl);
                        mma_bf16(acc[mt][n], a2l[mt][kt], bh);
                    }
                }
            }

            // ---- skip += s+bs ; h = h + r + br ----
            #pragma unroll
            for (int mt = 0; mt < 2; ++mt) {
                #pragma unroll
                for (int p = 0; p < 4; ++p) {
                    #pragma unroll
                    for (int half = 0; half < 2; ++half) {
                        const int rl = rb0 + mt*16 + half*8;
                        const int grow = g0 + rl;
                        const int c0 = p*8 + tig*2;
                        const int j0 = half*2;
                        float2 hp = bf2sum(aTh[mt][p>>1][(p&1)*2+half], aTl[mt][p>>1][(p&1)*2+half]);
                        skipacc[mt][p][j0]   += acc[mt][p][j0]   + bsm[64+c0];
                        skipacc[mt][p][j0+1] += acc[mt][p][j0+1] + bsm[64+c0+1];
                        float hv0 = hp.x + acc[mt][p+4][j0]   + bsm[96+c0];
                        float hv1 = hp.y + acc[mt][p+4][j0+1] + bsm[96+c0+1];
                        if (grow < 0) { hv0 = 0.f; hv1 = 0.f; }
                        uint32_t lo, hi = pack_hi(hv0, hv1, lo);
                        aTh[mt][p>>1][(p&1)*2+half] = hi;
                        aTl[mt][p>>1][(p&1)*2+half] = lo;
                        sH[rl*HSTR + p*4 + tig] = make_uint2(hi, lo);
                    }
                }
            }
            __syncthreads();
        }

        // ---- writeout ----
        #pragma unroll
        for (int mt = 0; mt < 2; ++mt) {
            #pragma unroll
            for (int p = 0; p < 4; ++p) {
                #pragma unroll
                for (int half = 0; half < 2; ++half) {
                    const int rl = rb0 + mt*16 + half*8;
                    if (rl >= 64) {
                        const int grow = g0 + rl;
                        if (grow < Ll) {
                            const int c0 = p*8 + tig*2;
                            const size_t i0 = (size_t)(b*Cc + c0)*Ll + grow;
                            g_skip[i0]      = skipacc[mt][p][half*2];
                            g_skip[i0 + Ll] = skipacc[mt][p][half*2 + 1];
                        }
                    }
                }
            }
        }
    }
}

// ---------------- downsample conv ----------------
__global__ void __launch_bounds__(256, 2)
downsample_kernel(const float* __restrict__ wd, const float* __restrict__ bd)
{
    extern __shared__ float smem[];
    float4* sWd = (float4*)smem;
    float*  sSk = smem + 8192;

    int tid = threadIdx.x;
    int b   = blockIdx.y;
    int u0  = blockIdx.x * 64;
    int t0  = u0 * 4;

    const float4* wd4 = (const float4*)wd;
    for (int e = tid; e < 2048; e += 256) sWd[e] = wd4[e];

    const float* skb = g_skip + (size_t)b * Cc * Ll;
    for (int e = tid; e < 32*256; e += 256) {
        int c = e >> 8, j = e & 255;
        int gt = t0 + j;
        sSk[c*256 + j] = (gt < Ll) ? skb[c*Ll + gt] : 0.0f;
    }
    __syncthreads();

    int op = tid >> 3;
    int o0 = op, o1 = op + 32;
    int qq = tid & 7;
    float a0[8], a1[8];
    float bd0 = bd[o0], bd1 = bd[o1];
    #pragma unroll
    for (int i = 0; i < 8; ++i) { a0[i]=bd0; a1[i]=bd1; }

    #pragma unroll 4
    for (int c = 0; c < 32; ++c) {
        float4 w0v = sWd[o0*32 + c];
        float4 w1v = sWd[o1*32 + c];
        const float* sr = sSk + c*256;
        #pragma unroll
        for (int i = 0; i < 8; ++i) {
            float4 sv = *(const float4*)(sr + (i*8 + qq)*4);
            a0[i] += w0v.x*sv.x + w0v.y*sv.y + w0v.z*sv.z + w0v.w*sv.w;
            a1[i] += w1v.x*sv.x + w1v.y*sv.y + w1v.z*sv.z + w1v.w*sv.w;
        }
    }
    float* yb = g_y + (size_t)b * FLATN;
    #pragma unroll
    for (int i = 0; i < 8; ++i) {
        int u = u0 + i*8 + qq;
        if (u < DOWNL) {
            yb[o0*DOWNL + u] = a0[i];
            yb[o1*DOWNL + u] = a1[i];
        }
    }
}

// ---------------- FC ----------------
__global__ void zero_o_kernel() {
    int i = threadIdx.x;
    if (i < Bb*64) g_o[i] = 0.0f;
}

#define FC_CHUNK 2000
__global__ void __launch_bounds__(512, 2)
fc_kernel(const float* __restrict__ fcW)
{
    extern __shared__ float smem[];
    int tid = threadIdx.x;
    int f0  = blockIdx.x * FC_CHUNK;
    int mg  = blockIdx.y;

    for (int e = tid; e < 8*FC_CHUNK/4; e += 512) {
        int b = e / (FC_CHUNK/4), f4 = e - b*(FC_CHUNK/4);
        ((float4*)smem)[b*(FC_CHUNK/4) + f4] =
            *(const float4*)(g_y + (size_t)b*FLATN + f0 + f4*4);
    }
    __syncthreads();

    int w = tid >> 5, lane = tid & 31;
    int m0 = mg*32 + w;
    float acc0[8], acc1[8];
    #pragma unroll
    for (int b = 0; b < 8; ++b) { acc0[b]=0.f; acc1[b]=0.f; }

    const float4* W0 = (const float4*)(fcW + (size_t)m0      * FLATN + f0);
    const float4* W1 = (const float4*)(fcW + (size_t)(m0+16) * FLATN + f0);
    #pragma unroll 2
    for (int i4 = lane; i4 < FC_CHUNK/4; i4 += 32) {
        float4 wv0 = __ldg(W0 + i4);
        float4 wv1 = __ldg(W1 + i4);
        #pragma unroll
        for (int b = 0; b < 8; ++b) {
            float4 yv = ((const float4*)smem)[b*(FC_CHUNK/4) + i4];
            acc0[b] += wv0.x*yv.x + wv0.y*yv.y + wv0.z*yv.z + wv0.w*yv.w;
            acc1[b] += wv1.x*yv.x + wv1.y*yv.y + wv1.z*yv.z + wv1.w*yv.w;
        }
    }
    #pragma unroll
    for (int off = 16; off; off >>= 1) {
        #pragma unroll
        for (int b = 0; b < 8; ++b) {
            acc0[b] += __shfl_xor_sync(0xFFFFFFFFu, acc0[b], off);
            acc1[b] += __shfl_xor_sync(0xFFFFFFFFu, acc1[b], off);
        }
    }
    if (lane == 0) {
        #pragma unroll
        for (int b = 0; b < 8; ++b) {
            atomicAdd(&g_o[b*64 + m0],      acc0[b]);
            atomicAdd(&g_o[b*64 + m0 + 16], acc1[b]);
        }
    }
}

// ---------------- final ----------------
__global__ void final_kernel(const float* __restrict__ eps,
                             const float* __restrict__ fcb,
                             float* __restrict__ out)
{
    int i = threadIdx.x;
    int b = i >> 5, l = i & 31;
    float mu = g_o[b*64 + l]      + fcb[l];
    float lv = g_o[b*64 + 32 + l] + fcb[32 + l];
    float z  = mu + eps[b*32 + l] * expf(0.5f * lv);
    out[i]       = mu;
    out[256 + i] = lv;
    out[512 + i] = z;
}

// ---------------- launch ----------------
extern "C" void kernel_launch(void* const* d_in, const int* in_sizes, int n_in,
                              void* d_out, int out_size)
{
    (void)in_sizes; (void)n_in; (void)out_size;
    const float* x   = (const float*)d_in[0];
    const float* eps = (const float*)d_in[1];
    const float* w0  = (const float*)d_in[2];
    const float* b0  = (const float*)d_in[3];
    const float* Wf  = (const float*)d_in[4];
    const float* bf  = (const float*)d_in[5];
    const float* Wg  = (const float*)d_in[6];
    const float* bg  = (const float*)d_in[7];
    const float* Ws  = (const float*)d_in[8];
    const float* bs  = (const float*)d_in[9];
    const float* Wr  = (const float*)d_in[10];
    const float* br  = (const float*)d_in[11];
    const float* wd  = (const float*)d_in[12];
    const float* bd  = (const float*)d_in[13];
    const float* fcW = (const float*)d_in[14];
    const float* fcb = (const float*)d_in[15];
    float* out = (float*)d_out;

    cudaFuncSetAttribute(wn_fused, cudaFuncAttributeMaxDynamicSharedMemorySize, SMEM_TOT);
    cudaFuncSetAttribute(downsample_kernel, cudaFuncAttributeMaxDynamicSharedMemorySize, 65536);
    cudaFuncSetAttribute(fc_kernel, cudaFuncAttributeMaxDynamicSharedMemorySize, 8*FC_CHUNK*4);

    wn_fused<<<GRIDP, NTHR, SMEM_TOT>>>(x, w0, b0, Wf, bf, Wg, bg, Ws, bs, Wr, br);
    downsample_kernel<<<dim3((DOWNL + 63)/64, Bb), 256, 65536>>>(wd, bd);
    zero_o_kernel<<<1, 512>>>();
    fc_kernel<<<dim3(FLATN/FC_CHUNK, 2), 512, 8*FC_CHUNK*4>>>(fcW);
    final_kernel<<<1, 256>>>(eps, fcb, out);
}

// round 10
// speedup vs baseline: 3.1613x; 1.0258x over previous
#include <cuda_runtime.h>
#include <cuda_bf16.h>
#include <cstdint>
#include <math.h>

#define Bb   8
#define Cc   32
#define Ll   90000
#define DOWNL 22500
#define FLATN 1440000

#define MT    3
#define TOUT  320
#define TPBT  282            // ceil(90000/320)
#define NT    (Bb*TPBT)      // 2256
#define GRIDP 148
#define NTHR  256

// ---- scratch ----
__device__ float g_skip[Bb*Cc*Ll];
__device__ float g_y[Bb*FLATN];
__device__ float g_o[Bb*64];

__device__ __forceinline__ void mma_bf16(float d[4], const uint32_t a[4], const uint32_t b[2]) {
    asm volatile(
        "mma.sync.aligned.m16n8k16.row.col.f32.bf16.bf16.f32 "
        "{%0,%1,%2,%3}, {%4,%5,%6,%7}, {%8,%9}, {%0,%1,%2,%3};"
        : "+f"(d[0]), "+f"(d[1]), "+f"(d[2]), "+f"(d[3])
        : "r"(a[0]), "r"(a[1]), "r"(a[2]), "r"(a[3]), "r"(b[0]), "r"(b[1]));
}
__device__ __forceinline__ uint32_t pack_hi(float a, float b, uint32_t& lo) {
    __nv_bfloat162 h2 = __floats2bfloat162_rn(a, b);
    float ra = a - __low2float(h2);
    float rb = b - __high2float(h2);
    __nv_bfloat162 l2 = __floats2bfloat162_rn(ra, rb);
    lo = *(uint32_t*)&l2;
    return *(uint32_t*)&h2;
}
__device__ __forceinline__ float2 bf2sum(uint32_t h, uint32_t l) {
    __nv_bfloat162 hh = *(__nv_bfloat162*)&h;
    __nv_bfloat162 ll = *(__nv_bfloat162*)&l;
    return make_float2(__bfloat162float(hh.x) + __bfloat162float(ll.x),
                       __bfloat162float(hh.y) + __bfloat162float(ll.y));
}
// o = tanh(f)*sigmoid(g) = (1-u)/((1+u)(1+v)), u=e^{-2f}, v=e^{-g}
__device__ __forceinline__ float gated(float f, float g) {
    f = fminf(fmaxf(f, -15.f), 15.f);
    g = fminf(fmaxf(g, -30.f), 30.f);
    float u = __expf(-2.f * f);
    float v = __expf(-g);
    return __fdividef(1.f - u, (1.f + u) * (1.f + v));
}
// swizzled sH addressing: conflict-free (rl ≡ r0 mod 4 in every phase)
__device__ __forceinline__ int h_word(int rl, int q) {
    return rl*16 + ((q + ((rl & 3) << 2)) & 15);
}

// ---- SMEM layout (bytes) ----
#define OFF_X     0          // 386 floats
#define OFF_CONV  1568       // 128 floats
#define OFF_BIAS  2080       // 768 floats
#define OFF_W1    5184       // 6 * uint2[64][36] = 110592
#define OFF_W2    115776     // 6 * uint2[64][20] = 61440
#define OFF_H     177216     // uint2[384][16] swizzled = 49152
#define SMEM_TOT  226368

#define W1STR 36
#define W2STR 20

// =========================================================================
// Fused conv0 + 6 blocks; 8 warps x m48, swizzled sH, nn-split GEMMs
// =========================================================================
__global__ void __launch_bounds__(NTHR)
wn_fused(const float* __restrict__ x,
         const float* __restrict__ w0g, const float* __restrict__ b0g,
         const float* __restrict__ Wf,  const float* __restrict__ bf,
         const float* __restrict__ Wg,  const float* __restrict__ bg,
         const float* __restrict__ Ws,  const float* __restrict__ bs,
         const float* __restrict__ Wr,  const float* __restrict__ br)
{
    extern __shared__ char sm[];
    float* sX    = (float*)(sm + OFF_X);
    float* sConv = (float*)(sm + OFF_CONV);
    float* sBias = (float*)(sm + OFF_BIAS);
    uint2* sW1   = (uint2*)(sm + OFF_W1);
    uint2* sW2   = (uint2*)(sm + OFF_W2);
    uint2* sH    = (uint2*)(sm + OFF_H);

    const int tid = threadIdx.x;

    for (int e = tid; e < 96; e += NTHR) sConv[e] = w0g[e];
    for (int e = tid; e < 32; e += NTHR) sConv[96 + e] = b0g[e];
    for (int e = tid; e < 6*128; e += NTHR) {
        int i = e >> 7, r = e & 127;
        float v = (r < 32)  ? bf[i*32 + r]
                : (r < 64)  ? bg[i*32 + r - 32]
                : (r < 96)  ? bs[i*32 + r - 64]
                :             br[i*32 + r - 96];
        sBias[e] = v;
    }
    for (int e = tid; e < 6*64*32; e += NTHR) {
        int i = e >> 11, rem = e & 2047;
        int n = rem >> 5, kp = rem & 31;
        const float* wfp = Wf + i*2048;
        const float* wgp = Wg + i*2048;
        float v[2];
        #pragma unroll
        for (int q = 0; q < 2; ++q) {
            int k = kp*2 + q;
            v[q] = (n < 32)
                ? ((k < 32) ? wfp[n*64 + k*2] : wfp[n*64 + (k-32)*2 + 1])
                : ((k < 32) ? wgp[(n-32)*64 + k*2] : wgp[(n-32)*64 + (k-32)*2 + 1]);
        }
        uint32_t lo, hi = pack_hi(v[0], v[1], lo);
        sW1[i*64*W1STR + n*W1STR + kp] = make_uint2(hi, lo);
    }
    for (int e = tid; e < 6*64*16; e += NTHR) {
        int i = e >> 10, rem = e & 1023;
        int n = rem >> 4, kp = rem & 15;
        const float* wsp = Ws + i*1024;
        const float* wrp = Wr + i*1024;
        float v0 = (n < 32) ? wsp[n*32 + kp*2]     : wrp[(n-32)*32 + kp*2];
        float v1 = (n < 32) ? wsp[n*32 + kp*2 + 1] : wrp[(n-32)*32 + kp*2 + 1];
        uint32_t lo, hi = pack_hi(v0, v1, lo);
        sW2[i*64*W2STR + n*W2STR + kp] = make_uint2(hi, lo);
    }
    __syncthreads();

    const int w    = tid >> 5;
    const int lane = tid & 31;
    const int r0   = lane >> 2;
    const int tig  = lane & 3;
    const int rb0  = w*48 + r0;      // rows rb0 + mt*16 + {0,8}, mt 0..2

    for (int tile = blockIdx.x; tile < NT; tile += GRIDP) {
        const int b  = tile / TPBT;
        const int u  = tile - b*TPBT;
        const int g0 = u*TOUT - 64;
        const float* xb = x + (size_t)b * Ll;

        for (int e = tid; e < 386; e += NTHR) {
            int gx = g0 - 2 + e;
            sX[e] = (gx >= 0 && gx < Ll) ? xb[gx] : 0.f;
        }
        __syncthreads();

        // ---- conv0 -> aT regs + sH ----
        uint32_t aTh[MT][2][4], aTl[MT][2][4];
        #pragma unroll
        for (int mt = 0; mt < MT; ++mt) {
            #pragma unroll
            for (int p = 0; p < 4; ++p) {
                #pragma unroll
                for (int half = 0; half < 2; ++half) {
                    const int rl = rb0 + mt*16 + half*8;
                    const int grow = g0 + rl;
                    float x0 = sX[rl+2], xm1 = sX[rl+1], xm2 = sX[rl];
                    const int c0 = p*8 + tig*2;
                    float v0 = sConv[c0*3+2]*x0 + sConv[c0*3+1]*xm1 + sConv[c0*3+0]*xm2 + sConv[96+c0];
                    float v1 = sConv[(c0+1)*3+2]*x0 + sConv[(c0+1)*3+1]*xm1 + sConv[(c0+1)*3+0]*xm2 + sConv[96+c0+1];
                    if (grow < 0 || grow >= Ll) { v0 = 0.f; v1 = 0.f; }
                    uint32_t lo, hi = pack_hi(v0, v1, lo);
                    aTh[mt][p>>1][(p&1)*2+half] = hi;
                    aTl[mt][p>>1][(p&1)*2+half] = lo;
                    sH[h_word(rl, p*4 + tig)] = make_uint2(hi, lo);
                }
            }
        }
        __syncthreads();

        float skipacc[MT][4][4];
        #pragma unroll
        for (int mt = 0; mt < MT; ++mt)
            #pragma unroll
            for (int n = 0; n < 4; ++n)
                #pragma unroll
                for (int j = 0; j < 4; ++j) skipacc[mt][n][j] = 0.f;

        #pragma unroll 1
        for (int i = 0; i < 6; ++i) {
            const int d = 1 << i;
            const uint2* W1b = sW1 + i*(64*W1STR);
            const uint2* W2b = sW2 + i*(64*W2STR);
            const float* bsm = sBias + i*128;

            // ============ GEMM1 (nn-split) + gated -> a2 ============
            uint32_t a2h[MT][2][4], a2l[MT][2][4];
            #pragma unroll
            for (int nn = 0; nn < 4; ++nn) {
                float acc[MT][2][4];
                #pragma unroll
                for (int mt = 0; mt < MT; ++mt)
                    #pragma unroll
                    for (int n2 = 0; n2 < 2; ++n2)
                        #pragma unroll
                        for (int j = 0; j < 4; ++j) acc[mt][n2][j] = 0.f;

                // dilated taps (weight cols kt 0..1), aD loaded from sH
                #pragma unroll
                for (int kt = 0; kt < 2; ++kt) {
                    uint32_t dh[MT][4], dl[MT][4];
                    #pragma unroll
                    for (int mt = 0; mt < MT; ++mt) {
                        int rlA = rb0 + mt*16 - d;     if (rlA < 0) rlA = 0;
                        int rlB = rb0 + mt*16 + 8 - d; if (rlB < 0) rlB = 0;
                        const int q = kt*8 + tig;
                        uint2 v00 = sH[h_word(rlA, q)];
                        uint2 v10 = sH[h_word(rlB, q)];
                        uint2 v01 = sH[h_word(rlA, q + 4)];
                        uint2 v11 = sH[h_word(rlB, q + 4)];
                        dh[mt][0] = v00.x; dh[mt][1] = v10.x; dh[mt][2] = v01.x; dh[mt][3] = v11.x;
                        dl[mt][0] = v00.y; dl[mt][1] = v10.y; dl[mt][2] = v01.y; dl[mt][3] = v11.y;
                    }
                    #pragma unroll
                    for (int n2 = 0; n2 < 2; ++n2) {
                        const int n = nn + n2*4;
                        uint2 wa = W1b[(n*8+r0)*W1STR + kt*8 + tig];
                        uint2 wb = W1b[(n*8+r0)*W1STR + kt*8 + tig + 4];
                        uint32_t bh[2] = { wa.x, wb.x };
                        uint32_t bl[2] = { wa.y, wb.y };
                        #pragma unroll
                        for (int mt = 0; mt < MT; ++mt) {
                            mma_bf16(acc[mt][n2], dh[mt], bh);
                            mma_bf16(acc[mt][n2], dh[mt], bl);
                            mma_bf16(acc[mt][n2], dl[mt], bh);
                        }
                    }
                }
                // current taps (weight cols kt 2..3), from held aT regs
                #pragma unroll
                for (int kt = 0; kt < 2; ++kt) {
                    #pragma unroll
                    for (int n2 = 0; n2 < 2; ++n2) {
                        const int n = nn + n2*4;
                        uint2 wa = W1b[(n*8+r0)*W1STR + (2+kt)*8 + tig];
                        uint2 wb = W1b[(n*8+r0)*W1STR + (2+kt)*8 + tig + 4];
                        uint32_t bh[2] = { wa.x, wb.x };
                        uint32_t bl[2] = { wa.y, wb.y };
                        #pragma unroll
                        for (int mt = 0; mt < MT; ++mt) {
                            mma_bf16(acc[mt][n2], aTh[mt][kt], bh);
                            mma_bf16(acc[mt][n2], aTh[mt][kt], bl);
                            mma_bf16(acc[mt][n2], aTl[mt][kt], bh);
                        }
                    }
                }
                // gated activation for this nn
                const int c = nn*8 + tig*2;
                const float b0f = bsm[c],    b1f = bsm[c+1];
                const float b0g = bsm[32+c], b1g = bsm[32+c+1];
                const int kt2 = nn >> 1;
                const int ri  = (nn & 1)*2;
                #pragma unroll
                for (int mt = 0; mt < MT; ++mt) {
                    float o0 = gated(acc[mt][0][0] + b0f, acc[mt][1][0] + b0g);
                    float o1 = gated(acc[mt][0][1] + b1f, acc[mt][1][1] + b1g);
                    float o2 = gated(acc[mt][0][2] + b0f, acc[mt][1][2] + b0g);
                    float o3 = gated(acc[mt][0][3] + b1f, acc[mt][1][3] + b1g);
                    a2h[mt][kt2][ri]     = pack_hi(o0, o1, a2l[mt][kt2][ri]);
                    a2h[mt][kt2][ri + 1] = pack_hi(o2, o3, a2l[mt][kt2][ri + 1]);
                }
            }
            __syncthreads();   // all GEMM1 sH reads done before h writes below

            // ============ GEMM2 (nn-split) + skip/h update ============
            #pragma unroll
            for (int nn = 0; nn < 4; ++nn) {
                float acc[MT][2][4];
                #pragma unroll
                for (int mt = 0; mt < MT; ++mt)
                    #pragma unroll
                    for (int n2 = 0; n2 < 2; ++n2)
                        #pragma unroll
                        for (int j = 0; j < 4; ++j) acc[mt][n2][j] = 0.f;

                #pragma unroll
                for (int kt = 0; kt < 2; ++kt) {
                    #pragma unroll
                    for (int n2 = 0; n2 < 2; ++n2) {
                        const int n = nn + n2*4;
                        uint2 wa = W2b[(n*8+r0)*W2STR + kt*8 + tig];
                        uint2 wb = W2b[(n*8+r0)*W2STR + kt*8 + tig + 4];
                        uint32_t bh[2] = { wa.x, wb.x };
                        uint32_t bl[2] = { wa.y, wb.y };
                        #pragma unroll
                        for (int mt = 0; mt < MT; ++mt) {
                            mma_bf16(acc[mt][n2], a2h[mt][kt], bh);
                            mma_bf16(acc[mt][n2], a2h[mt][kt], bl);
                            mma_bf16(acc[mt][n2], a2l[mt][kt], bh);
                        }
                    }
                }
                const int c0 = nn*8 + tig*2;
                const int kt2 = nn >> 1;
                const int ri  = (nn & 1)*2;
                #pragma unroll
                for (int mt = 0; mt < MT; ++mt) {
                    #pragma unroll
                    for (int half = 0; half < 2; ++half) {
                        const int rl = rb0 + mt*16 + half*8;
                        const int grow = g0 + rl;
                        const int j0 = half*2;
                        float2 hp = bf2sum(aTh[mt][kt2][ri+half], aTl[mt][kt2][ri+half]);
                        skipacc[mt][nn][j0]   += acc[mt][0][j0]   + bsm[64+c0];
                        skipacc[mt][nn][j0+1] += acc[mt][0][j0+1] + bsm[64+c0+1];
                        if (i < 5) {
                            float hv0 = hp.x + acc[mt][1][j0]   + bsm[96+c0];
                            float hv1 = hp.y + acc[mt][1][j0+1] + bsm[96+c0+1];
                            if (grow < 0) { hv0 = 0.f; hv1 = 0.f; }
                            uint32_t lo, hi = pack_hi(hv0, hv1, lo);
                            aTh[mt][kt2][ri+half] = hi;
                            aTl[mt][kt2][ri+half] = lo;
                            sH[h_word(rl, nn*4 + tig)] = make_uint2(hi, lo);
                        }
                    }
                }
            }
            if (i < 5) __syncthreads();   // h_{i+1} visible for next block
        }

        // ---- writeout ----
        #pragma unroll
        for (int mt = 0; mt < MT; ++mt) {
            #pragma unroll
            for (int p = 0; p < 4; ++p) {
                #pragma unroll
                for (int half = 0; half < 2; ++half) {
                    const int rl = rb0 + mt*16 + half*8;
                    if (rl >= 64) {
                        const int grow = g0 + rl;
                        if (grow < Ll) {
                            const int c0 = p*8 + tig*2;
                            const size_t i0 = (size_t)(b*Cc + c0)*Ll + grow;
                            g_skip[i0]      = skipacc[mt][p][half*2];
                            g_skip[i0 + Ll] = skipacc[mt][p][half*2 + 1];
                        }
                    }
                }
            }
        }
    }
}

// ---------------- downsample conv ----------------
__global__ void __launch_bounds__(256)
downsample_kernel(const float* __restrict__ wd, const float* __restrict__ bd)
{
    extern __shared__ float sSk[];     // [32][256] = 32 KB

    int tid = threadIdx.x;
    int b   = blockIdx.y;
    int u0  = blockIdx.x * 64;
    int t0  = u0 * 4;

    const float* skb = g_skip + (size_t)b * Cc * Ll;
    for (int e = tid; e < 32*256; e += 256) {
        int c = e >> 8, j = e & 255;
        int gt = t0 + j;
        sSk[c*256 + j] = (gt < Ll) ? skb[c*Ll + gt] : 0.0f;
    }
    __syncthreads();

    const float4* wd4 = (const float4*)wd;
    int op = tid >> 3;
    int o0 = op, o1 = op + 32;
    int qq = tid & 7;
    float a0[8], a1[8];
    float bd0 = __ldg(bd + o0), bd1 = __ldg(bd + o1);
    #pragma unroll
    for (int i = 0; i < 8; ++i) { a0[i]=bd0; a1[i]=bd1; }

    #pragma unroll 4
    for (int c = 0; c < 32; ++c) {
        float4 w0v = __ldg(wd4 + o0*32 + c);
        float4 w1v = __ldg(wd4 + o1*32 + c);
        const float* sr = sSk + c*256;
        #pragma unroll
        for (int i = 0; i < 8; ++i) {
            float4 sv = *(const float4*)(sr + (i*8 + qq)*4);
            a0[i] += w0v.x*sv.x + w0v.y*sv.y + w0v.z*sv.z + w0v.w*sv.w;
            a1[i] += w1v.x*sv.x + w1v.y*sv.y + w1v.z*sv.z + w1v.w*sv.w;
        }
    }
    float* yb = g_y + (size_t)b * FLATN;
    #pragma unroll
    for (int i = 0; i < 8; ++i) {
        int u = u0 + i*8 + qq;
        if (u < DOWNL) {
            yb[o0*DOWNL + u] = a0[i];
            yb[o1*DOWNL + u] = a1[i];
        }
    }
}

// ---------------- FC ----------------
__global__ void zero_o_kernel() {
    int i = threadIdx.x;
    if (i < Bb*64) g_o[i] = 0.0f;
}

#define FC_CHUNK 2000
__global__ void __launch_bounds__(512)
fc_kernel(const float* __restrict__ fcW)
{
    extern __shared__ float smem[];      // y[8][2000]
    int tid = threadIdx.x;
    int f0  = blockIdx.x * FC_CHUNK;

    for (int e = tid; e < 8*FC_CHUNK/4; e += 512) {
        int b = e / (FC_CHUNK/4), f4 = e - b*(FC_CHUNK/4);
        ((float4*)smem)[b*(FC_CHUNK/4) + f4] =
            *(const float4*)(g_y + (size_t)b*FLATN + f0 + f4*4);
    }
    __syncthreads();

    int w = tid >> 5, lane = tid & 31;
    float acc[4][8];
    #pragma unroll
    for (int q = 0; q < 4; ++q)
        #pragma unroll
        for (int b = 0; b < 8; ++b) acc[q][b] = 0.f;

    const float4* W0 = (const float4*)(fcW + (size_t)(w     ) * FLATN + f0);
    const float4* W1 = (const float4*)(fcW + (size_t)(w + 16) * FLATN + f0);
    const float4* W2 = (const float4*)(fcW + (size_t)(w + 32) * FLATN + f0);
    const float4* W3 = (const float4*)(fcW + (size_t)(w + 48) * FLATN + f0);
    #pragma unroll 2
    for (int i4 = lane; i4 < FC_CHUNK/4; i4 += 32) {
        float4 wv0 = __ldg(W0 + i4);
        float4 wv1 = __ldg(W1 + i4);
        float4 wv2 = __ldg(W2 + i4);
        float4 wv3 = __ldg(W3 + i4);
        #pragma unroll
        for (int b = 0; b < 8; ++b) {
            float4 yv = ((const float4*)smem)[b*(FC_CHUNK/4) + i4];
            acc[0][b] += wv0.x*yv.x + wv0.y*yv.y + wv0.z*yv.z + wv0.w*yv.w;
            acc[1][b] += wv1.x*yv.x + wv1.y*yv.y + wv1.z*yv.z + wv1.w*yv.w;
            acc[2][b] += wv2.x*yv.x + wv2.y*yv.y + wv2.z*yv.z + wv2.w*yv.w;
            acc[3][b] += wv3.x*yv.x + wv3.y*yv.y + wv3.z*yv.z + wv3.w*yv.w;
        }
    }
    #pragma unroll
    for (int off = 16; off; off >>= 1)
        #pragma unroll
        for (int q = 0; q < 4; ++q)
            #pragma unroll
            for (int b = 0; b < 8; ++b)
                acc[q][b] += __shfl_xor_sync(0xFFFFFFFFu, acc[q][b], off);
    if (lane == 0) {
        #pragma unroll
        for (int q = 0; q < 4; ++q)
            #pragma unroll
            for (int b = 0; b < 8; ++b)
                atomicAdd(&g_o[b*64 + w + q*16], acc[q][b]);
    }
}

// ---------------- final ----------------
__global__ void final_kernel(const float* __restrict__ eps,
                             const float* __restrict__ fcb,
                             float* __restrict__ out)
{
    int i = threadIdx.x;
    int b = i >> 5, l = i & 31;
    float mu = g_o[b*64 + l]      + fcb[l];
    float lv = g_o[b*64 + 32 + l] + fcb[32 + l];
    float z  = mu + eps[b*32 + l] * expf(0.5f * lv);
    out[i]       = mu;
    out[256 + i] = lv;
    out[512 + i] = z;
}

// ---------------- launch ----------------
extern "C" void kernel_launch(void* const* d_in, const int* in_sizes, int n_in,
                              void* d_out, int out_size)
{
    (void)in_sizes; (void)n_in; (void)out_size;
    const float* x   = (const float*)d_in[0];
    const float* eps = (const float*)d_in[1];
    const float* w0  = (const float*)d_in[2];
    const float* b0  = (const float*)d_in[3];
    const float* Wf  = (const float*)d_in[4];
    const float* bf  = (const float*)d_in[5];
    const float* Wg  = (const float*)d_in[6];
    const float* bg  = (const float*)d_in[7];
    const float* Ws  = (const float*)d_in[8];
    const float* bs  = (const float*)d_in[9];
    const float* Wr  = (const float*)d_in[10];
    const float* br  = (const float*)d_in[11];
    const float* wd  = (const float*)d_in[12];
    const float* bd  = (const float*)d_in[13];
    const float* fcW = (const float*)d_in[14];
    const float* fcb = (const float*)d_in[15];
    float* out = (float*)d_out;

    cudaFuncSetAttribute(wn_fused, cudaFuncAttributeMaxDynamicSharedMemorySize, SMEM_TOT);
    cudaFuncSetAttribute(downsample_kernel, cudaFuncAttributeMaxDynamicSharedMemorySize, 32768);
    cudaFuncSetAttribute(fc_kernel, cudaFuncAttributeMaxDynamicSharedMemorySize, 8*FC_CHUNK*4);

    wn_fused<<<GRIDP, NTHR, SMEM_TOT>>>(x, w0, b0, Wf, bf, Wg, bg, Ws, bs, Wr, br);
    downsample_kernel<<<dim3((DOWNL + 63)/64, Bb), 256, 32768>>>(wd, bd);
    zero_o_kernel<<<1, 512>>>();
    fc_kernel<<<FLATN/FC_CHUNK, 512, 8*FC_CHUNK*4>>>(fcW);
    final_kernel<<<1, 256>>>(eps, fcb, out);
}